// round 1
// baseline (speedup 1.0000x reference)
#include <cuda_runtime.h>
#include <cstddef>

// ---------------------------------------------------------------------------
// Problem constants
// ---------------------------------------------------------------------------
#define cB 32
#define cS 2304
#define cD 1280
#define cDEPTH 6
#define cH 16
#define cHD 96
#define cL 64
#define cI 5120
#define cT (cS + cL)      /* 2368 */
#define cHHD (cH * cHD)   /* 1536 */
#define cEPS 1e-5f

// ---------------------------------------------------------------------------
// Scratch (device globals: allocation-free rule)
// ---------------------------------------------------------------------------
__device__ float g_nctx[(size_t)cB * cS * cD];        // normalized context (no affine)
__device__ float g_lat[cB * cL * cD];                 // latent state
__device__ float g_latln[cB * cL * cD];               // LN(latents)
__device__ float g_Q[cB * cL * cHHD];                 // Q projections
__device__ float g_K[(size_t)cB * cT * cHHD];         // K for [context; latents]
__device__ float g_V[(size_t)cB * cT * cHHD];         // V for [context; latents]
__device__ float g_scores[(size_t)cB * cH * cL * cT]; // attention scores / probs
__device__ float g_att[cB * cL * cHHD];               // attention output (B,L,H*HD)
__device__ float g_mlp[cB * cL * cI];                 // MLP hidden

// ---------------------------------------------------------------------------
// Broadcast latents -> (B, L, D)
// ---------------------------------------------------------------------------
__global__ void bcast_latents_kernel(const float* __restrict__ lat,
                                     float* __restrict__ out) {
  int idx = blockIdx.x * 256 + threadIdx.x;   // grid sized exactly
  out[idx] = lat[idx % (cL * cD)];
}

// ---------------------------------------------------------------------------
// LayerNorm over rows of length ncols (block per row).
// g == nullptr -> store pure normalized value (no affine).
// ---------------------------------------------------------------------------
__global__ void ln_rows_kernel(const float* __restrict__ x, float* __restrict__ y,
                               const float* __restrict__ g,
                               const float* __restrict__ b, int ncols) {
  int row = blockIdx.x;
  const float* xr = x + (size_t)row * ncols;
  float* yr = y + (size_t)row * ncols;
  float s = 0.f, s2 = 0.f;
  for (int c = threadIdx.x; c < ncols; c += blockDim.x) {
    float v = xr[c];
    s += v;
    s2 += v * v;
  }
  __shared__ float sh[64];
  for (int o = 16; o; o >>= 1) {
    s += __shfl_xor_sync(0xffffffffu, s, o);
    s2 += __shfl_xor_sync(0xffffffffu, s2, o);
  }
  int w = threadIdx.x >> 5, lane = threadIdx.x & 31;
  if (lane == 0) { sh[w] = s; sh[w + 32] = s2; }
  __syncthreads();
  if (w == 0) {
    int nw = blockDim.x >> 5;
    s = (lane < nw) ? sh[lane] : 0.f;
    s2 = (lane < nw) ? sh[lane + 32] : 0.f;
    for (int o = 16; o; o >>= 1) {
      s += __shfl_xor_sync(0xffffffffu, s, o);
      s2 += __shfl_xor_sync(0xffffffffu, s2, o);
    }
    if (lane == 0) { sh[0] = s; sh[1] = s2; }
  }
  __syncthreads();
  float inv_n = 1.f / (float)ncols;
  float mean = sh[0] * inv_n;
  float var = sh[1] * inv_n - mean * mean;
  float rstd = rsqrtf(var + cEPS);
  if (g != nullptr) {
    for (int c = threadIdx.x; c < ncols; c += blockDim.x)
      yr[c] = (xr[c] - mean) * rstd * g[c] + b[c];
  } else {
    for (int c = threadIdx.x; c < ncols; c += blockDim.x)
      yr[c] = (xr[c] - mean) * rstd;
  }
}

// ---------------------------------------------------------------------------
// Per-head LN over contiguous 96-element subrows (warp per row, in place).
// ---------------------------------------------------------------------------
__global__ void ln_head_kernel(float* x, const float* __restrict__ g,
                               const float* __restrict__ b, int nrows) {
  int r = blockIdx.x * 4 + (threadIdx.x >> 5);
  if (r >= nrows) return;
  int lane = threadIdx.x & 31;
  float* xr = x + (size_t)r * cHD;
  float v0 = xr[lane], v1 = xr[lane + 32], v2 = xr[lane + 64];
  float s = v0 + v1 + v2;
  float s2 = v0 * v0 + v1 * v1 + v2 * v2;
  for (int o = 16; o; o >>= 1) {
    s += __shfl_xor_sync(0xffffffffu, s, o);
    s2 += __shfl_xor_sync(0xffffffffu, s2, o);
  }
  float mean = s * (1.f / 96.f);
  float rstd = rsqrtf(s2 * (1.f / 96.f) - mean * mean + cEPS);
  xr[lane]      = (v0 - mean) * rstd * g[lane]      + b[lane];
  xr[lane + 32] = (v1 - mean) * rstd * g[lane + 32] + b[lane + 32];
  xr[lane + 64] = (v2 - mean) * rstd * g[lane + 64] + b[lane + 64];
}

// ---------------------------------------------------------------------------
// Tiled SGEMM: C[M,N] = op(A')[M,K] @ B[K,N]  (+R, relu optional)
//   A'(m,k) = A(m,k)*ag[k] + ab[k]  when ag != nullptr (fused context affine)
//   Output row remap: orow = (m / rpbIn)*rpbOut + rowOff + (m % rpbIn)
// 128x128x16 tile, 256 threads, 8x8 per thread. M%128==0, N%128==0, K%16==0.
// ---------------------------------------------------------------------------
__global__ __launch_bounds__(256) void sgemm128(
    const float* __restrict__ A, const float* __restrict__ Bm, float* C,
    int M, int N, int K,
    const float* __restrict__ ag, const float* __restrict__ ab,
    const float* R, int relu, int rpbIn, int rpbOut, int rowOff) {
  __shared__ __align__(16) float As[16][132];  // transposed, padded
  __shared__ __align__(16) float Bs[16][128];

  int tid = threadIdx.x;
  int m0 = blockIdx.y * 128;
  int n0 = blockIdx.x * 128;

  float acc[8][8];
#pragma unroll
  for (int i = 0; i < 8; i++)
#pragma unroll
    for (int j = 0; j < 8; j++) acc[i][j] = 0.f;

  int tm = (tid >> 4) << 3;
  int tn = (tid & 15) << 3;

  for (int kk = 0; kk < K; kk += 16) {
    // load A tile (with optional per-k affine), store transposed
#pragma unroll
    for (int i = 0; i < 2; i++) {
      int e = tid + i * 256;
      int m = e >> 2, kq = (e & 3) << 2;
      float4 v = *(const float4*)(A + (size_t)(m0 + m) * K + kk + kq);
      if (ag != nullptr) {
        float4 g4 = *(const float4*)(ag + kk + kq);
        float4 b4 = *(const float4*)(ab + kk + kq);
        v.x = v.x * g4.x + b4.x;
        v.y = v.y * g4.y + b4.y;
        v.z = v.z * g4.z + b4.z;
        v.w = v.w * g4.w + b4.w;
      }
      As[kq + 0][m] = v.x;
      As[kq + 1][m] = v.y;
      As[kq + 2][m] = v.z;
      As[kq + 3][m] = v.w;
    }
    // load B tile
#pragma unroll
    for (int i = 0; i < 2; i++) {
      int e = tid + i * 256;
      int k = e >> 5, n4 = (e & 31) << 2;
      *(float4*)&Bs[k][n4] = *(const float4*)(Bm + (size_t)(kk + k) * N + n0 + n4);
    }
    __syncthreads();
#pragma unroll
    for (int k = 0; k < 16; k++) {
      float a[8], bb[8];
      *(float4*)&a[0] = *(const float4*)&As[k][tm];
      *(float4*)&a[4] = *(const float4*)&As[k][tm + 4];
      *(float4*)&bb[0] = *(const float4*)&Bs[k][tn];
      *(float4*)&bb[4] = *(const float4*)&Bs[k][tn + 4];
#pragma unroll
      for (int i = 0; i < 8; i++)
#pragma unroll
        for (int j = 0; j < 8; j++) acc[i][j] += a[i] * bb[j];
    }
    __syncthreads();
  }

#pragma unroll
  for (int i = 0; i < 8; i++) {
    int m = m0 + tm + i;
    int orow = (m / rpbIn) * rpbOut + rowOff + (m % rpbIn);
    float* crow = C + (size_t)orow * N + n0 + tn;
    const float* rrow = (R != nullptr) ? (R + (size_t)orow * N + n0 + tn) : nullptr;
#pragma unroll
    for (int j = 0; j < 8; j++) {
      float v = acc[i][j];
      if (R != nullptr) v += rrow[j];
      if (relu) v = fmaxf(v, 0.f);
      crow[j] = v;
    }
  }
}

// ---------------------------------------------------------------------------
// Attention scores: Sc[bh, l, t] = scale * sum_d qln[b,l,h,d] * kln[b,t,h,d]
// grid (37, B*H), block 256, dynamic smem: 2 * 64*97 floats
// ---------------------------------------------------------------------------
#define SC_SMEM (2 * 64 * 97 * 4)
__global__ __launch_bounds__(256) void attn_scores_kernel(
    const float* __restrict__ Q, const float* __restrict__ K,
    float* __restrict__ Sc) {
  extern __shared__ float sm[];
  float(*qs)[97] = (float(*)[97])sm;
  float(*ks)[97] = (float(*)[97])(sm + 64 * 97);
  int bh = blockIdx.y;
  int b = bh >> 4, h = bh & 15;
  int t0 = blockIdx.x * 64;
  const float* Qb = Q + (size_t)(b * cL) * cHHD + h * cHD;
  const float* Kb = K + (size_t)(b * cT + t0) * cHHD + h * cHD;
  for (int idx = threadIdx.x; idx < 64 * 96; idx += 256) {
    int r = idx / 96, c = idx % 96;
    qs[r][c] = Qb[(size_t)r * cHHD + c];
    ks[r][c] = Kb[(size_t)r * cHHD + c];
  }
  __syncthreads();
  int lh = threadIdx.x >> 4, th = threadIdx.x & 15;
  float acc[4][4];
#pragma unroll
  for (int i = 0; i < 4; i++)
#pragma unroll
    for (int j = 0; j < 4; j++) acc[i][j] = 0.f;
#pragma unroll 4
  for (int d = 0; d < 96; d++) {
    float qv[4], kv[4];
#pragma unroll
    for (int i = 0; i < 4; i++) {
      qv[i] = qs[lh * 4 + i][d];
      kv[i] = ks[th * 4 + i][d];
    }
#pragma unroll
    for (int i = 0; i < 4; i++)
#pragma unroll
      for (int j = 0; j < 4; j++) acc[i][j] += qv[i] * kv[j];
  }
  const float scale = 0.102062072615966f;  // 96^-0.5
#pragma unroll
  for (int i = 0; i < 4; i++)
#pragma unroll
    for (int j = 0; j < 4; j++)
      Sc[((size_t)bh * cL + lh * 4 + i) * cT + t0 + th * 4 + j] =
          acc[i][j] * scale;
}

// ---------------------------------------------------------------------------
// Row softmax over length 2368 (block per row, in place).
// ---------------------------------------------------------------------------
__global__ void softmax_rows_kernel(float* Sc) {
  float* x = Sc + (size_t)blockIdx.x * cT;
  int tid = threadIdx.x;
  __shared__ float sh[32];
  __shared__ float bcast;
  // max
  float m = -1e30f;
  for (int c = tid; c < cT; c += 256) m = fmaxf(m, x[c]);
  for (int o = 16; o; o >>= 1) m = fmaxf(m, __shfl_xor_sync(0xffffffffu, m, o));
  int w = tid >> 5, lane = tid & 31;
  if (lane == 0) sh[w] = m;
  __syncthreads();
  if (w == 0) {
    m = (lane < 8) ? sh[lane] : -1e30f;
    for (int o = 16; o; o >>= 1) m = fmaxf(m, __shfl_xor_sync(0xffffffffu, m, o));
    if (lane == 0) bcast = m;
  }
  __syncthreads();
  m = bcast;
  // exp + sum
  float s = 0.f;
  for (int c = tid; c < cT; c += 256) {
    float e = __expf(x[c] - m);
    x[c] = e;
    s += e;
  }
  for (int o = 16; o; o >>= 1) s += __shfl_xor_sync(0xffffffffu, s, o);
  __syncthreads();
  if (lane == 0) sh[w] = s;
  __syncthreads();
  if (w == 0) {
    s = (lane < 8) ? sh[lane] : 0.f;
    for (int o = 16; o; o >>= 1) s += __shfl_xor_sync(0xffffffffu, s, o);
    if (lane == 0) bcast = 1.f / s;
  }
  __syncthreads();
  float inv = bcast;
  for (int c = tid; c < cT; c += 256) x[c] *= inv;
}

// ---------------------------------------------------------------------------
// attn @ V: out[b, l, h*96+d] = sum_t P[bh, l, t] * V[b, t, h*96+d]
// grid B*H (512), block 256.
// ---------------------------------------------------------------------------
__global__ __launch_bounds__(256) void attn_av_kernel(
    const float* __restrict__ P, const float* __restrict__ V,
    float* __restrict__ O) {
  __shared__ float ps[64][65];
  __shared__ float vs[64][97];
  int bh = blockIdx.x;
  int b = bh >> 4, h = bh & 15;
  int lh = threadIdx.x >> 4, dh = threadIdx.x & 15;
  float acc[4][6];
#pragma unroll
  for (int i = 0; i < 4; i++)
#pragma unroll
    for (int j = 0; j < 6; j++) acc[i][j] = 0.f;

  const float* Pb = P + (size_t)bh * cL * cT;
  const float* Vb = V + (size_t)b * cT * cHHD + h * cHD;

  for (int ct = 0; ct < 37; ct++) {
    int t0 = ct * 64;
    for (int idx = threadIdx.x; idx < 64 * 64; idx += 256) {
      int r = idx >> 6, c = idx & 63;
      ps[r][c] = Pb[(size_t)r * cT + t0 + c];
    }
    for (int idx = threadIdx.x; idx < 64 * 96; idx += 256) {
      int r = idx / 96, c = idx % 96;
      vs[r][c] = Vb[(size_t)(t0 + r) * cHHD + c];
    }
    __syncthreads();
#pragma unroll 4
    for (int tt = 0; tt < 64; tt++) {
      float pv[4], vv[6];
#pragma unroll
      for (int i = 0; i < 4; i++) pv[i] = ps[lh * 4 + i][tt];
#pragma unroll
      for (int j = 0; j < 6; j++) vv[j] = vs[tt][dh * 6 + j];
#pragma unroll
      for (int i = 0; i < 4; i++)
#pragma unroll
        for (int j = 0; j < 6; j++) acc[i][j] += pv[i] * vv[j];
    }
    __syncthreads();
  }
#pragma unroll
  for (int i = 0; i < 4; i++)
#pragma unroll
    for (int j = 0; j < 6; j++)
      O[(size_t)(b * cL + lh * 4 + i) * cHHD + h * cHD + dh * 6 + j] = acc[i][j];
}

// ---------------------------------------------------------------------------
// Host orchestration
// ---------------------------------------------------------------------------
extern "C" void kernel_launch(void* const* d_in, const int* in_sizes, int n_in,
                              void* d_out, int out_size) {
  (void)in_sizes; (void)n_in; (void)out_size;
  const float* context = (const float*)d_in[0];
  const float* latents = (const float*)d_in[1];
  const float* ctx_g = (const float*)d_in[2];
  const float* ctx_b = (const float*)d_in[3];
  const float* lat_g = (const float*)d_in[4];
  const float* lat_b = (const float*)d_in[5];
  const float* q_g = (const float*)d_in[6];
  const float* q_b = (const float*)d_in[7];
  const float* k_g = (const float*)d_in[8];
  const float* k_b = (const float*)d_in[9];
  const float* Wq = (const float*)d_in[10];
  const float* Wk = (const float*)d_in[11];
  const float* Wv = (const float*)d_in[12];
  const float* Wo = (const float*)d_in[13];
  const float* mlp_g = (const float*)d_in[14];
  const float* mlp_b = (const float*)d_in[15];
  const float* Wfc = (const float*)d_in[16];
  const float* Wcp = (const float*)d_in[17];
  const float* f_g = (const float*)d_in[18];
  const float* f_b = (const float*)d_in[19];
  float* out = (float*)d_out;

  float *nctx, *lat, *latln, *Qp, *Kp, *Vp, *Scp, *Attp, *Mlpp;
  cudaGetSymbolAddress((void**)&nctx, g_nctx);
  cudaGetSymbolAddress((void**)&lat, g_lat);
  cudaGetSymbolAddress((void**)&latln, g_latln);
  cudaGetSymbolAddress((void**)&Qp, g_Q);
  cudaGetSymbolAddress((void**)&Kp, g_K);
  cudaGetSymbolAddress((void**)&Vp, g_V);
  cudaGetSymbolAddress((void**)&Scp, g_scores);
  cudaGetSymbolAddress((void**)&Attp, g_att);
  cudaGetSymbolAddress((void**)&Mlpp, g_mlp);

  cudaFuncSetAttribute(attn_scores_kernel,
                       cudaFuncAttributeMaxDynamicSharedMemorySize, SC_SMEM);

  const int ML = cB * cL;  // 2048 latent rows

  // once: normalized context (no affine), latent broadcast
  ln_rows_kernel<<<cB * cS, 256>>>(context, nctx, nullptr, nullptr, cD);
  bcast_latents_kernel<<<(ML * cD) / 256, 256>>>(latents, lat);

  auto gemm = [&](const float* A, const float* Bm, float* C, int M, int N,
                  int Kd, const float* ag, const float* ab, const float* R,
                  int relu, int rpbIn, int rpbOut, int rowOff) {
    dim3 grid(N / 128, M / 128);
    sgemm128<<<grid, 256>>>(A, Bm, C, M, N, Kd, ag, ab, R, relu, rpbIn, rpbOut,
                            rowOff);
  };

  for (int i = 0; i < cDEPTH; i++) {
    const float* Wq_i = Wq + (size_t)i * cD * cHHD;
    const float* Wk_i = Wk + (size_t)i * cD * cHHD;
    const float* Wv_i = Wv + (size_t)i * cD * cHHD;
    const float* Wo_i = Wo + (size_t)i * cHHD * cD;
    const float* Wfc_i = Wfc + (size_t)i * cD * cI;
    const float* Wcp_i = Wcp + (size_t)i * cI * cD;

    // LN(latents)
    ln_rows_kernel<<<ML, 256>>>(lat, latln, lat_g + i * cD, lat_b + i * cD, cD);

    // Q = latln @ Wq
    gemm(latln, Wq_i, Qp, ML, cHHD, cD, nullptr, nullptr, nullptr, 0, ML, ML, 0);

    // K, V for context (fused ctx LN affine) and latents (row-remapped to tail)
    gemm(nctx, Wk_i, Kp, cB * cS, cHHD, cD, ctx_g + i * cD, ctx_b + i * cD,
         nullptr, 0, cS, cT, 0);
    gemm(latln, Wk_i, Kp, ML, cHHD, cD, nullptr, nullptr, nullptr, 0, cL, cT, cS);
    gemm(nctx, Wv_i, Vp, cB * cS, cHHD, cD, ctx_g + i * cD, ctx_b + i * cD,
         nullptr, 0, cS, cT, 0);
    gemm(latln, Wv_i, Vp, ML, cHHD, cD, nullptr, nullptr, nullptr, 0, cL, cT, cS);

    // per-head q/k LN (in place)
    ln_head_kernel<<<(ML * cH) / 4, 128>>>(Qp, q_g + i * cHD, q_b + i * cHD,
                                           ML * cH);
    ln_head_kernel<<<(cB * cT * cH) / 4, 128>>>(Kp, k_g + i * cHD,
                                                k_b + i * cHD, cB * cT * cH);

    // attention
    attn_scores_kernel<<<dim3(cT / 64, cB * cH), 256, SC_SMEM>>>(Qp, Kp, Scp);
    softmax_rows_kernel<<<cB * cH * cL, 256>>>(Scp);
    attn_av_kernel<<<cB * cH, 256>>>(Scp, Vp, Attp);

    // lat = att @ Wo + lat
    gemm(Attp, Wo_i, lat, ML, cD, cHHD, nullptr, nullptr, lat, 0, ML, ML, 0);

    // MLP
    ln_rows_kernel<<<ML, 256>>>(lat, latln, mlp_g + i * cD, mlp_b + i * cD, cD);
    gemm(latln, Wfc_i, Mlpp, ML, cI, cD, nullptr, nullptr, nullptr, 1, ML, ML, 0);
    gemm(Mlpp, Wcp_i, lat, ML, cD, cI, nullptr, nullptr, lat, 0, ML, ML, 0);
  }

  // final LN -> output
  ln_rows_kernel<<<ML, 256>>>(lat, out, f_g, f_b, cD);
}

// round 3
// speedup vs baseline: 1.7643x; 1.7643x over previous
#include <cuda_runtime.h>
#include <cuda_bf16.h>
#include <cstdint>
#include <cstddef>

// ---------------------------------------------------------------------------
// Problem constants
// ---------------------------------------------------------------------------
#define cB 32
#define cS 2304
#define cD 1280
#define cDEPTH 6
#define cH 16
#define cHD 96
#define cL 64
#define cI 5120
#define cT (cS + cL)      /* 2368 */
#define cHHD (cH * cHD)   /* 1536 */
#define cEPS 1e-5f
#define cMCTX (cB * cS)   /* 73728 ctx rows */

// ---------------------------------------------------------------------------
// Scratch (device globals: allocation-free rule)
// ---------------------------------------------------------------------------
__device__ __nv_bfloat16 g_ctx_hi[(size_t)cMCTX * cD];  // LN(ctx) bf16 high
__device__ __nv_bfloat16 g_ctx_lo[(size_t)cMCTX * cD];  // LN(ctx) bf16 low
__device__ __nv_bfloat16 g_wkt_hi[cHHD * cD];           // (g.Wk)^T hi  [N][K]
__device__ __nv_bfloat16 g_wkt_lo[cHHD * cD];
__device__ __nv_bfloat16 g_wvt_hi[cHHD * cD];
__device__ __nv_bfloat16 g_wvt_lo[cHHD * cD];
__device__ float g_biasK[cHHD];                         // b . Wk
__device__ float g_biasV[cHHD];
__device__ float g_lat[cB * cL * cD];
__device__ float g_latln[cB * cL * cD];
__device__ float g_Q[cB * cL * cHHD];
__device__ float g_K[(size_t)cB * cT * cHHD];
__device__ float g_V[(size_t)cB * cT * cHHD];
__device__ float g_scores[(size_t)cB * cH * cL * cT];
__device__ float g_att[cB * cL * cHHD];
__device__ float g_mlp[cB * cL * cI];

// ---------------------------------------------------------------------------
// MMA helpers (base-PTX only: ldmatrix + mma.sync, sm_80+)
// ---------------------------------------------------------------------------
__device__ __forceinline__ uint32_t smem_u32(const void* p) {
  uint32_t a;
  asm("{ .reg .u64 t; cvta.to.shared.u64 t, %1; cvt.u32.u64 %0, t; }"
      : "=r"(a) : "l"(p));
  return a;
}
__device__ __forceinline__ void cp_async16(uint32_t saddr, const void* gptr) {
  asm volatile("cp.async.cg.shared.global [%0], [%1], 16;" ::"r"(saddr),
               "l"(gptr)
               : "memory");
}
#define CP_COMMIT() asm volatile("cp.async.commit_group;" ::: "memory")
#define CP_WAIT(N) asm volatile("cp.async.wait_group %0;" ::"n"(N) : "memory")

__device__ __forceinline__ void ldsm_x4(uint32_t* d, uint32_t addr) {
  asm volatile("ldmatrix.sync.aligned.m8n8.x4.shared.b16 {%0,%1,%2,%3},[%4];"
               : "=r"(d[0]), "=r"(d[1]), "=r"(d[2]), "=r"(d[3])
               : "r"(addr));
}
__device__ __forceinline__ void ldsm_x2(uint32_t* d, uint32_t addr) {
  asm volatile("ldmatrix.sync.aligned.m8n8.x2.shared.b16 {%0,%1},[%2];"
               : "=r"(d[0]), "=r"(d[1])
               : "r"(addr));
}
__device__ __forceinline__ void mma16816(float* c, const uint32_t* a,
                                         const uint32_t* b) {
  asm volatile(
      "mma.sync.aligned.m16n8k16.row.col.f32.bf16.bf16.f32 "
      "{%0,%1,%2,%3},{%4,%5,%6,%7},{%8,%9},{%0,%1,%2,%3};"
      : "+f"(c[0]), "+f"(c[1]), "+f"(c[2]), "+f"(c[3])
      : "r"(a[0]), "r"(a[1]), "r"(a[2]), "r"(a[3]), "r"(b[0]), "r"(b[1]));
}

// ---------------------------------------------------------------------------
// Pipelined bf16-split MMA GEMM for the context K/V projections.
//   C[orow(m), n] = sum_k A(m,k)*B(n,k) + bias[n]
//   A = ctx hi/lo [73728][1280], B = weight hi/lo [1536][1280] (K-contiguous)
//   3-term split: hi*hi + hi*lo + lo*hi  (error ~2^-16)
//   orow(m) = (m/cS)*cT + m%cS  (context rows of the [S+L] concatenation)
// Tile 128x128, BK=32, 256 thr (8 warps, warp tile 64x32), cp.async 2-stage.
// ---------------------------------------------------------------------------
#define MG_BK 32
#define MG_NC (cD / MG_BK) /* 40 */
#define MG_STRIDE 40       /* bf16 elems per smem row (pad 8) -> 80B */
#define MG_ARR (128 * MG_STRIDE * 2) /* 10240 B per array */
#define MG_BUF (4 * MG_ARR)          /* 40960 B per stage */
#define MG_SMEM (2 * MG_BUF)         /* 81920 B */

__global__ __launch_bounds__(256) void mma_gemm_split(
    const __nv_bfloat16* __restrict__ Ahi, const __nv_bfloat16* __restrict__ Alo,
    const __nv_bfloat16* __restrict__ Bhi, const __nv_bfloat16* __restrict__ Blo,
    const float* __restrict__ bias, float* __restrict__ C) {
  extern __shared__ char sm[];
  const uint32_t sb = smem_u32(sm);
  const int tid = threadIdx.x;
  const int lane = tid & 31, wid = tid >> 5;
  const int wm = wid & 1, wn = wid >> 1;  // 2 x 4 warp grid
  const int m0 = blockIdx.y * 128, n0 = blockIdx.x * 128;

  const __nv_bfloat16* gA0 = Ahi + (size_t)m0 * cD;
  const __nv_bfloat16* gA1 = Alo + (size_t)m0 * cD;
  const __nv_bfloat16* gB0 = Bhi + (size_t)n0 * cD;
  const __nv_bfloat16* gB1 = Blo + (size_t)n0 * cD;

  float acc[4][4][4];
#pragma unroll
  for (int mt = 0; mt < 4; mt++)
#pragma unroll
    for (int nt = 0; nt < 4; nt++)
#pragma unroll
      for (int j = 0; j < 4; j++) acc[mt][nt][j] = 0.f;

  // per-thread load slots: e = tid + j*256 -> row e>>2, 16B unit e&3
  const int lr = tid >> 2;           // rows for j=0 slot (0..63)
  const int lu = tid & 3;            // 16B unit
  // j=1 slot: rows 64..127
  auto load_chunk = [&](int c, int buf) {
    int kk = c * MG_BK;
    uint32_t base = sb + buf * MG_BUF;
#pragma unroll
    for (int j = 0; j < 2; j++) {
      int r = lr + j * 64;
      uint32_t so = r * (MG_STRIDE * 2) + lu * 16;
      size_t go = (size_t)r * cD + kk + lu * 8;
      cp_async16(base + 0 * MG_ARR + so, gA0 + go);
      cp_async16(base + 1 * MG_ARR + so, gA1 + go);
      cp_async16(base + 2 * MG_ARR + so, gB0 + go);
      cp_async16(base + 3 * MG_ARR + so, gB1 + go);
    }
    CP_COMMIT();
  };

  load_chunk(0, 0);

  // ldmatrix address components (bytes)
  const uint32_t aRow = (wm * 64 + (lane & 15)) * (MG_STRIDE * 2);
  const uint32_t aColB = ((lane >> 4) << 3) * 2;
  const uint32_t bRow = (wn * 32 + (lane & 7)) * (MG_STRIDE * 2);
  const uint32_t bColB = (((lane >> 3) & 1) << 3) * 2;

  for (int c = 0; c < MG_NC; c++) {
    int buf = c & 1;
    if (c + 1 < MG_NC) {
      load_chunk(c + 1, buf ^ 1);
      CP_WAIT(1);
    } else {
      CP_WAIT(0);
    }
    __syncthreads();
    uint32_t base = sb + buf * MG_BUF;
#pragma unroll
    for (int ks = 0; ks < 2; ks++) {
      uint32_t kb = ks * 32;  // 16 bf16 = 32 bytes
      uint32_t ah[4][4], al[4][4], bh[4][2], bl[4][2];
#pragma unroll
      for (int mt = 0; mt < 4; mt++) {
        uint32_t ad = base + aRow + mt * 16 * (MG_STRIDE * 2) + kb + aColB;
        ldsm_x4(ah[mt], ad);
        ldsm_x4(al[mt], ad + MG_ARR);
      }
#pragma unroll
      for (int nt = 0; nt < 4; nt++) {
        uint32_t bd = base + 2 * MG_ARR + bRow + nt * 8 * (MG_STRIDE * 2) + kb + bColB;
        ldsm_x2(bh[nt], bd);
        ldsm_x2(bl[nt], bd + MG_ARR);
      }
#pragma unroll
      for (int mt = 0; mt < 4; mt++)
#pragma unroll
        for (int nt = 0; nt < 4; nt++) {
          mma16816(acc[mt][nt], ah[mt], bh[nt]);
          mma16816(acc[mt][nt], ah[mt], bl[nt]);
          mma16816(acc[mt][nt], al[mt], bh[nt]);
        }
    }
    __syncthreads();
  }

  // epilogue: bias + row remap, float2 stores
#pragma unroll
  for (int mt = 0; mt < 4; mt++) {
    int m = m0 + wm * 64 + mt * 16 + (lane >> 2);
    int or0 = (m / cS) * cT + (m % cS);
    int or1 = ((m + 8) / cS) * cT + ((m + 8) % cS);
#pragma unroll
    for (int nt = 0; nt < 4; nt++) {
      int n = n0 + wn * 32 + nt * 8 + (lane & 3) * 2;
      float b0 = bias[n], b1 = bias[n + 1];
      float2 v0 = make_float2(acc[mt][nt][0] + b0, acc[mt][nt][1] + b1);
      float2 v1 = make_float2(acc[mt][nt][2] + b0, acc[mt][nt][3] + b1);
      *(float2*)(C + (size_t)or0 * cHHD + n) = v0;
      *(float2*)(C + (size_t)or1 * cHHD + n) = v1;
    }
  }
}

// ---------------------------------------------------------------------------
// ctx LN + bf16 hi/lo split (once): row mean/var, no affine
// ---------------------------------------------------------------------------
__global__ void ctx_ln_split_kernel(const float* __restrict__ x,
                                    __nv_bfloat16* __restrict__ hi,
                                    __nv_bfloat16* __restrict__ lo) {
  int row = blockIdx.x;
  const float* xr = x + (size_t)row * cD;
  float s = 0.f, s2 = 0.f;
  for (int c = threadIdx.x; c < cD; c += 256) {
    float v = xr[c];
    s += v; s2 += v * v;
  }
  __shared__ float sh[64];
  for (int o = 16; o; o >>= 1) {
    s += __shfl_xor_sync(~0u, s, o);
    s2 += __shfl_xor_sync(~0u, s2, o);
  }
  int w = threadIdx.x >> 5, lane = threadIdx.x & 31;
  if (lane == 0) { sh[w] = s; sh[w + 32] = s2; }
  __syncthreads();
  if (w == 0) {
    s = (lane < 8) ? sh[lane] : 0.f;
    s2 = (lane < 8) ? sh[lane + 32] : 0.f;
    for (int o = 16; o; o >>= 1) {
      s += __shfl_xor_sync(~0u, s, o);
      s2 += __shfl_xor_sync(~0u, s2, o);
    }
    if (lane == 0) { sh[0] = s; sh[1] = s2; }
  }
  __syncthreads();
  float mean = sh[0] * (1.f / cD);
  float rstd = rsqrtf(sh[1] * (1.f / cD) - mean * mean + cEPS);
  for (int c = threadIdx.x; c < cD; c += 256) {
    float v = (xr[c] - mean) * rstd;
    __nv_bfloat16 h = __float2bfloat16(v);
    hi[(size_t)row * cD + c] = h;
    lo[(size_t)row * cD + c] = __float2bfloat16(v - __bfloat162float(h));
  }
}

// ---------------------------------------------------------------------------
// Weight prep: Wt[n][k] = g[k]*W[k][n] bf16 hi/lo, bias[n] = sum_k b[k]*W[k][n]
// ---------------------------------------------------------------------------
__global__ void wprep_kernel(const float* __restrict__ W,
                             const float* __restrict__ g,
                             const float* __restrict__ b,
                             __nv_bfloat16* __restrict__ Whi,
                             __nv_bfloat16* __restrict__ Wlo,
                             float* __restrict__ bias) {
  int n = blockIdx.x;
  float bs = 0.f;
  for (int k = threadIdx.x; k < cD; k += 256) {
    float w = W[(size_t)k * cHHD + n];
    float v = g[k] * w;
    __nv_bfloat16 h = __float2bfloat16(v);
    Whi[(size_t)n * cD + k] = h;
    Wlo[(size_t)n * cD + k] = __float2bfloat16(v - __bfloat162float(h));
    bs += b[k] * w;
  }
  __shared__ float sh[8];
  for (int o = 16; o; o >>= 1) bs += __shfl_xor_sync(~0u, bs, o);
  int w8 = threadIdx.x >> 5, lane = threadIdx.x & 31;
  if (lane == 0) sh[w8] = bs;
  __syncthreads();
  if (threadIdx.x == 0) {
    float t = 0.f;
    for (int i = 0; i < 8; i++) t += sh[i];
    bias[n] = t;
  }
}

// ---------------------------------------------------------------------------
// Broadcast latents -> (B, L, D)
// ---------------------------------------------------------------------------
__global__ void bcast_latents_kernel(const float* __restrict__ lat,
                                     float* __restrict__ out) {
  int idx = blockIdx.x * 256 + threadIdx.x;
  out[idx] = lat[idx % (cL * cD)];
}

// ---------------------------------------------------------------------------
// LayerNorm over rows (block per row)
// ---------------------------------------------------------------------------
__global__ void ln_rows_kernel(const float* __restrict__ x, float* __restrict__ y,
                               const float* __restrict__ g,
                               const float* __restrict__ b, int ncols) {
  int row = blockIdx.x;
  const float* xr = x + (size_t)row * ncols;
  float* yr = y + (size_t)row * ncols;
  float s = 0.f, s2 = 0.f;
  for (int c = threadIdx.x; c < ncols; c += blockDim.x) {
    float v = xr[c];
    s += v; s2 += v * v;
  }
  __shared__ float sh[64];
  for (int o = 16; o; o >>= 1) {
    s += __shfl_xor_sync(~0u, s, o);
    s2 += __shfl_xor_sync(~0u, s2, o);
  }
  int w = threadIdx.x >> 5, lane = threadIdx.x & 31;
  if (lane == 0) { sh[w] = s; sh[w + 32] = s2; }
  __syncthreads();
  if (w == 0) {
    int nw = blockDim.x >> 5;
    s = (lane < nw) ? sh[lane] : 0.f;
    s2 = (lane < nw) ? sh[lane + 32] : 0.f;
    for (int o = 16; o; o >>= 1) {
      s += __shfl_xor_sync(~0u, s, o);
      s2 += __shfl_xor_sync(~0u, s2, o);
    }
    if (lane == 0) { sh[0] = s; sh[1] = s2; }
  }
  __syncthreads();
  float mean = sh[0] / (float)ncols;
  float rstd = rsqrtf(sh[1] / (float)ncols - mean * mean + cEPS);
  for (int c = threadIdx.x; c < ncols; c += blockDim.x)
    yr[c] = (xr[c] - mean) * rstd * g[c] + b[c];
}

// ---------------------------------------------------------------------------
// Per-head LN over 96-element subrows (warp per row, in place)
// ---------------------------------------------------------------------------
__global__ void ln_head_kernel(float* x, const float* __restrict__ g,
                               const float* __restrict__ b, int nrows) {
  int r = blockIdx.x * 4 + (threadIdx.x >> 5);
  if (r >= nrows) return;
  int lane = threadIdx.x & 31;
  float* xr = x + (size_t)r * cHD;
  float v0 = xr[lane], v1 = xr[lane + 32], v2 = xr[lane + 64];
  float s = v0 + v1 + v2;
  float s2 = v0 * v0 + v1 * v1 + v2 * v2;
  for (int o = 16; o; o >>= 1) {
    s += __shfl_xor_sync(~0u, s, o);
    s2 += __shfl_xor_sync(~0u, s2, o);
  }
  float mean = s * (1.f / 96.f);
  float rstd = rsqrtf(s2 * (1.f / 96.f) - mean * mean + cEPS);
  xr[lane]      = (v0 - mean) * rstd * g[lane]      + b[lane];
  xr[lane + 32] = (v1 - mean) * rstd * g[lane + 32] + b[lane + 32];
  xr[lane + 64] = (v2 - mean) * rstd * g[lane + 64] + b[lane + 64];
}

// ---------------------------------------------------------------------------
// fp32 tiled SGEMM (small GEMMs): C = A@B (+R, relu), output row remap
// ---------------------------------------------------------------------------
__global__ __launch_bounds__(256) void sgemm128(
    const float* __restrict__ A, const float* __restrict__ Bm, float* C,
    int M, int N, int K, const float* R, int relu, int rpbIn, int rpbOut,
    int rowOff) {
  __shared__ __align__(16) float As[16][132];
  __shared__ __align__(16) float Bs[16][128];
  int tid = threadIdx.x;
  int m0 = blockIdx.y * 128, n0 = blockIdx.x * 128;
  float acc[8][8];
#pragma unroll
  for (int i = 0; i < 8; i++)
#pragma unroll
    for (int j = 0; j < 8; j++) acc[i][j] = 0.f;
  int tm = (tid >> 4) << 3, tn = (tid & 15) << 3;
  for (int kk = 0; kk < K; kk += 16) {
#pragma unroll
    for (int i = 0; i < 2; i++) {
      int e = tid + i * 256;
      int m = e >> 2, kq = (e & 3) << 2;
      float4 v = *(const float4*)(A + (size_t)(m0 + m) * K + kk + kq);
      As[kq + 0][m] = v.x; As[kq + 1][m] = v.y;
      As[kq + 2][m] = v.z; As[kq + 3][m] = v.w;
    }
#pragma unroll
    for (int i = 0; i < 2; i++) {
      int e = tid + i * 256;
      int k = e >> 5, n4 = (e & 31) << 2;
      *(float4*)&Bs[k][n4] = *(const float4*)(Bm + (size_t)(kk + k) * N + n0 + n4);
    }
    __syncthreads();
#pragma unroll
    for (int k = 0; k < 16; k++) {
      float a[8], bb[8];
      *(float4*)&a[0] = *(const float4*)&As[k][tm];
      *(float4*)&a[4] = *(const float4*)&As[k][tm + 4];
      *(float4*)&bb[0] = *(const float4*)&Bs[k][tn];
      *(float4*)&bb[4] = *(const float4*)&Bs[k][tn + 4];
#pragma unroll
      for (int i = 0; i < 8; i++)
#pragma unroll
        for (int j = 0; j < 8; j++) acc[i][j] += a[i] * bb[j];
    }
    __syncthreads();
  }
#pragma unroll
  for (int i = 0; i < 8; i++) {
    int m = m0 + tm + i;
    int orow = (m / rpbIn) * rpbOut + rowOff + (m % rpbIn);
    float* crow = C + (size_t)orow * N + n0 + tn;
    const float* rrow = (R != nullptr) ? (R + (size_t)orow * N + n0 + tn) : nullptr;
#pragma unroll
    for (int j = 0; j < 8; j++) {
      float v = acc[i][j];
      if (R != nullptr) v += rrow[j];
      if (relu) v = fmaxf(v, 0.f);
      crow[j] = v;
    }
  }
}

// ---------------------------------------------------------------------------
// Attention scores: Sc[bh,l,t] = scale * q.k
// ---------------------------------------------------------------------------
#define SC_SMEM (2 * 64 * 97 * 4)
__global__ __launch_bounds__(256) void attn_scores_kernel(
    const float* __restrict__ Q, const float* __restrict__ K,
    float* __restrict__ Sc) {
  extern __shared__ float smf[];
  float(*qs)[97] = (float(*)[97])smf;
  float(*ks)[97] = (float(*)[97])(smf + 64 * 97);
  int bh = blockIdx.y;
  int b = bh >> 4, h = bh & 15;
  int t0 = blockIdx.x * 64;
  const float* Qb = Q + (size_t)(b * cL) * cHHD + h * cHD;
  const float* Kb = K + (size_t)(b * cT + t0) * cHHD + h * cHD;
  for (int idx = threadIdx.x; idx < 64 * 96; idx += 256) {
    int r = idx / 96, c = idx % 96;
    qs[r][c] = Qb[(size_t)r * cHHD + c];
    ks[r][c] = Kb[(size_t)r * cHHD + c];
  }
  __syncthreads();
  int lh = threadIdx.x >> 4, th = threadIdx.x & 15;
  float acc[4][4];
#pragma unroll
  for (int i = 0; i < 4; i++)
#pragma unroll
    for (int j = 0; j < 4; j++) acc[i][j] = 0.f;
#pragma unroll 4
  for (int d = 0; d < 96; d++) {
    float qv[4], kv[4];
#pragma unroll
    for (int i = 0; i < 4; i++) {
      qv[i] = qs[lh * 4 + i][d];
      kv[i] = ks[th * 4 + i][d];
    }
#pragma unroll
    for (int i = 0; i < 4; i++)
#pragma unroll
      for (int j = 0; j < 4; j++) acc[i][j] += qv[i] * kv[j];
  }
  const float scale = 0.102062072615966f;
#pragma unroll
  for (int i = 0; i < 4; i++)
#pragma unroll
    for (int j = 0; j < 4; j++)
      Sc[((size_t)bh * cL + lh * 4 + i) * cT + t0 + th * 4 + j] =
          acc[i][j] * scale;
}

// ---------------------------------------------------------------------------
// Row softmax over 2368 (block per row, in place)
// ---------------------------------------------------------------------------
__global__ void softmax_rows_kernel(float* Sc) {
  float* x = Sc + (size_t)blockIdx.x * cT;
  int tid = threadIdx.x;
  __shared__ float sh[32];
  __shared__ float bc;
  float m = -1e30f;
  for (int c = tid; c < cT; c += 256) m = fmaxf(m, x[c]);
  for (int o = 16; o; o >>= 1) m = fmaxf(m, __shfl_xor_sync(~0u, m, o));
  int w = tid >> 5, lane = tid & 31;
  if (lane == 0) sh[w] = m;
  __syncthreads();
  if (w == 0) {
    m = (lane < 8) ? sh[lane] : -1e30f;
    for (int o = 16; o; o >>= 1) m = fmaxf(m, __shfl_xor_sync(~0u, m, o));
    if (lane == 0) bc = m;
  }
  __syncthreads();
  m = bc;
  float s = 0.f;
  for (int c = tid; c < cT; c += 256) {
    float e = __expf(x[c] - m);
    x[c] = e;
    s += e;
  }
  for (int o = 16; o; o >>= 1) s += __shfl_xor_sync(~0u, s, o);
  __syncthreads();
  if (lane == 0) sh[w] = s;
  __syncthreads();
  if (w == 0) {
    s = (lane < 8) ? sh[lane] : 0.f;
    for (int o = 16; o; o >>= 1) s += __shfl_xor_sync(~0u, s, o);
    if (lane == 0) bc = 1.f / s;
  }
  __syncthreads();
  float inv = bc;
  for (int c = tid; c < cT; c += 256) x[c] *= inv;
}

// ---------------------------------------------------------------------------
// attn @ V
// ---------------------------------------------------------------------------
__global__ __launch_bounds__(256) void attn_av_kernel(
    const float* __restrict__ P, const float* __restrict__ V,
    float* __restrict__ O) {
  __shared__ float ps[64][65];
  __shared__ float vs[64][97];
  int bh = blockIdx.x;
  int b = bh >> 4, h = bh & 15;
  int lh = threadIdx.x >> 4, dh = threadIdx.x & 15;
  float acc[4][6];
#pragma unroll
  for (int i = 0; i < 4; i++)
#pragma unroll
    for (int j = 0; j < 6; j++) acc[i][j] = 0.f;
  const float* Pb = P + (size_t)bh * cL * cT;
  const float* Vb = V + (size_t)b * cT * cHHD + h * cHD;
  for (int ct = 0; ct < 37; ct++) {
    int t0 = ct * 64;
    for (int idx = threadIdx.x; idx < 64 * 64; idx += 256) {
      int r = idx >> 6, c = idx & 63;
      ps[r][c] = Pb[(size_t)r * cT + t0 + c];
    }
    for (int idx = threadIdx.x; idx < 64 * 96; idx += 256) {
      int r = idx / 96, c = idx % 96;
      vs[r][c] = Vb[(size_t)(t0 + r) * cHHD + c];
    }
    __syncthreads();
#pragma unroll 4
    for (int tt = 0; tt < 64; tt++) {
      float pv[4], vv[6];
#pragma unroll
      for (int i = 0; i < 4; i++) pv[i] = ps[lh * 4 + i][tt];
#pragma unroll
      for (int j = 0; j < 6; j++) vv[j] = vs[tt][dh * 6 + j];
#pragma unroll
      for (int i = 0; i < 4; i++)
#pragma unroll
        for (int j = 0; j < 6; j++) acc[i][j] += pv[i] * vv[j];
    }
    __syncthreads();
  }
#pragma unroll
  for (int i = 0; i < 4; i++)
#pragma unroll
    for (int j = 0; j < 6; j++)
      O[(size_t)(b * cL + lh * 4 + i) * cHHD + h * cHD + dh * 6 + j] = acc[i][j];
}

// ---------------------------------------------------------------------------
// Host orchestration
// ---------------------------------------------------------------------------
extern "C" void kernel_launch(void* const* d_in, const int* in_sizes, int n_in,
                              void* d_out, int out_size) {
  (void)in_sizes; (void)n_in; (void)out_size;
  const float* context = (const float*)d_in[0];
  const float* latents = (const float*)d_in[1];
  const float* ctx_g = (const float*)d_in[2];
  const float* ctx_b = (const float*)d_in[3];
  const float* lat_g = (const float*)d_in[4];
  const float* lat_b = (const float*)d_in[5];
  const float* q_g = (const float*)d_in[6];
  const float* q_b = (const float*)d_in[7];
  const float* k_g = (const float*)d_in[8];
  const float* k_b = (const float*)d_in[9];
  const float* Wq = (const float*)d_in[10];
  const float* Wk = (const float*)d_in[11];
  const float* Wv = (const float*)d_in[12];
  const float* Wo = (const float*)d_in[13];
  const float* mlp_g = (const float*)d_in[14];
  const float* mlp_b = (const float*)d_in[15];
  const float* Wfc = (const float*)d_in[16];
  const float* Wcp = (const float*)d_in[17];
  const float* f_g = (const float*)d_in[18];
  const float* f_b = (const float*)d_in[19];
  float* out = (float*)d_out;

  __nv_bfloat16 *ctxhi, *ctxlo, *wkthi, *wktlo, *wvthi, *wvtlo;
  float *biasK, *biasV, *lat, *latln, *Qp, *Kp, *Vp, *Scp, *Attp, *Mlpp;
  cudaGetSymbolAddress((void**)&ctxhi, g_ctx_hi);
  cudaGetSymbolAddress((void**)&ctxlo, g_ctx_lo);
  cudaGetSymbolAddress((void**)&wkthi, g_wkt_hi);
  cudaGetSymbolAddress((void**)&wktlo, g_wkt_lo);
  cudaGetSymbolAddress((void**)&wvthi, g_wvt_hi);
  cudaGetSymbolAddress((void**)&wvtlo, g_wvt_lo);
  cudaGetSymbolAddress((void**)&biasK, g_biasK);
  cudaGetSymbolAddress((void**)&biasV, g_biasV);
  cudaGetSymbolAddress((void**)&lat, g_lat);
  cudaGetSymbolAddress((void**)&latln, g_latln);
  cudaGetSymbolAddress((void**)&Qp, g_Q);
  cudaGetSymbolAddress((void**)&Kp, g_K);
  cudaGetSymbolAddress((void**)&Vp, g_V);
  cudaGetSymbolAddress((void**)&Scp, g_scores);
  cudaGetSymbolAddress((void**)&Attp, g_att);
  cudaGetSymbolAddress((void**)&Mlpp, g_mlp);

  cudaFuncSetAttribute(attn_scores_kernel,
                       cudaFuncAttributeMaxDynamicSharedMemorySize, SC_SMEM);
  cudaFuncSetAttribute(mma_gemm_split,
                       cudaFuncAttributeMaxDynamicSharedMemorySize, MG_SMEM);

  const int ML = cB * cL;

  // once: LN(context) -> bf16 hi/lo ; latent broadcast
  ctx_ln_split_kernel<<<cMCTX, 256>>>(context, ctxhi, ctxlo);
  bcast_latents_kernel<<<(ML * cD) / 256, 256>>>(latents, lat);

  auto gemm = [&](const float* A, const float* Bm, float* C, int M, int N,
                  int Kd, const float* R, int relu, int rpbIn, int rpbOut,
                  int rowOff) {
    dim3 grid(N / 128, M / 128);
    sgemm128<<<grid, 256>>>(A, Bm, C, M, N, Kd, R, relu, rpbIn, rpbOut, rowOff);
  };

  dim3 mgGrid(cHHD / 128, cMCTX / 128);  // (12, 576)

  for (int i = 0; i < cDEPTH; i++) {
    const float* Wq_i = Wq + (size_t)i * cD * cHHD;
    const float* Wk_i = Wk + (size_t)i * cD * cHHD;
    const float* Wv_i = Wv + (size_t)i * cD * cHHD;
    const float* Wo_i = Wo + (size_t)i * cHHD * cD;
    const float* Wfc_i = Wfc + (size_t)i * cD * cI;
    const float* Wcp_i = Wcp + (size_t)i * cI * cD;

    // LN(latents)
    ln_rows_kernel<<<ML, 256>>>(lat, latln, lat_g + i * cD, lat_b + i * cD, cD);

    // Q = latln @ Wq (fp32)
    gemm(latln, Wq_i, Qp, ML, cHHD, cD, nullptr, 0, ML, ML, 0);

    // K/V context projections on tensor cores (bf16 hi/lo, LN affine folded)
    wprep_kernel<<<cHHD, 256>>>(Wk_i, ctx_g + i * cD, ctx_b + i * cD, wkthi,
                                wktlo, biasK);
    mma_gemm_split<<<mgGrid, 256, MG_SMEM>>>(ctxhi, ctxlo, wkthi, wktlo, biasK,
                                             Kp);
    wprep_kernel<<<cHHD, 256>>>(Wv_i, ctx_g + i * cD, ctx_b + i * cD, wvthi,
                                wvtlo, biasV);
    mma_gemm_split<<<mgGrid, 256, MG_SMEM>>>(ctxhi, ctxlo, wvthi, wvtlo, biasV,
                                             Vp);

    // latent rows of K/V (fp32, original weights, rows appended at offset cS)
    gemm(latln, Wk_i, Kp, ML, cHHD, cD, nullptr, 0, cL, cT, cS);
    gemm(latln, Wv_i, Vp, ML, cHHD, cD, nullptr, 0, cL, cT, cS);

    // per-head q/k LN
    ln_head_kernel<<<(ML * cH) / 4, 128>>>(Qp, q_g + i * cHD, q_b + i * cHD,
                                           ML * cH);
    ln_head_kernel<<<(cB * cT * cH) / 4, 128>>>(Kp, k_g + i * cHD,
                                                k_b + i * cHD, cB * cT * cH);

    // attention
    attn_scores_kernel<<<dim3(cT / 64, cB * cH), 256, SC_SMEM>>>(Qp, Kp, Scp);
    softmax_rows_kernel<<<cB * cH * cL, 256>>>(Scp);
    attn_av_kernel<<<cB * cH, 256>>>(Scp, Vp, Attp);

    // lat = att @ Wo + lat
    gemm(Attp, Wo_i, lat, ML, cD, cHHD, lat, 0, ML, ML, 0);

    // MLP
    ln_rows_kernel<<<ML, 256>>>(lat, latln, mlp_g + i * cD, mlp_b + i * cD, cD);
    gemm(latln, Wfc_i, Mlpp, ML, cI, cD, nullptr, 1, ML, ML, 0);
    gemm(Mlpp, Wcp_i, lat, ML, cD, cI, lat, 0, ML, ML, 0);
  }

  ln_rows_kernel<<<ML, 256>>>(lat, out, f_g, f_b, cD);
}

// round 4
// speedup vs baseline: 2.0377x; 1.1549x over previous
#include <cuda_runtime.h>
#include <cuda_bf16.h>
#include <cstdint>
#include <cstddef>

// ---------------------------------------------------------------------------
// Problem constants
// ---------------------------------------------------------------------------
#define cB 32
#define cS 2304
#define cD 1280
#define cDEPTH 6
#define cH 16
#define cHD 96
#define cL 64
#define cI 5120
#define cT (cS + cL)      /* 2368 */
#define cHHD (cH * cHD)   /* 1536 */
#define cEPS 1e-5f
#define cMCTX (cB * cS)   /* 73728 ctx rows */
#define cML (cB * cL)     /* 2048 latent rows */

// ---------------------------------------------------------------------------
// Scratch (device globals: allocation-free rule)
// ---------------------------------------------------------------------------
__device__ __nv_bfloat16 g_ctx_hi[(size_t)cMCTX * cD];
__device__ __nv_bfloat16 g_ctx_lo[(size_t)cMCTX * cD];
__device__ __nv_bfloat16 g_latln_hi[cML * cD];
__device__ __nv_bfloat16 g_latln_lo[cML * cD];
__device__ __nv_bfloat16 g_att_hi[cML * cHHD];
__device__ __nv_bfloat16 g_att_lo[cML * cHHD];
__device__ __nv_bfloat16 g_mlp_hi[(size_t)cML * cI];
__device__ __nv_bfloat16 g_mlp_lo[(size_t)cML * cI];
// transposed (folded) weights, hi/lo
__device__ __nv_bfloat16 g_wq_hi[cHHD * cD],  g_wq_lo[cHHD * cD];
__device__ __nv_bfloat16 g_wkc_hi[cHHD * cD], g_wkc_lo[cHHD * cD];
__device__ __nv_bfloat16 g_wkl_hi[cHHD * cD], g_wkl_lo[cHHD * cD];
__device__ __nv_bfloat16 g_wvc_hi[cHHD * cD], g_wvc_lo[cHHD * cD];
__device__ __nv_bfloat16 g_wvl_hi[cHHD * cD], g_wvl_lo[cHHD * cD];
__device__ __nv_bfloat16 g_wo_hi[cD * cHHD],  g_wo_lo[cD * cHHD];
__device__ __nv_bfloat16 g_wfc_hi[(size_t)cI * cD], g_wfc_lo[(size_t)cI * cD];
__device__ __nv_bfloat16 g_wcp_hi[(size_t)cD * cI], g_wcp_lo[(size_t)cD * cI];
__device__ float g_biasQ[cHHD], g_biasKc[cHHD], g_biasKl[cHHD];
__device__ float g_biasVc[cHHD], g_biasVl[cHHD], g_biasFc[cI];
__device__ float g_lat[cML * cD];
__device__ float g_Q[cML * cHHD];
__device__ float g_K[(size_t)cB * cT * cHHD];
__device__ float g_V[(size_t)cB * cT * cHHD];
__device__ float g_scores[(size_t)cB * cH * cL * cT];

// ---------------------------------------------------------------------------
// MMA helpers (base-PTX: ldmatrix + mma.sync, sm_80+)
// ---------------------------------------------------------------------------
__device__ __forceinline__ uint32_t smem_u32(const void* p) {
  uint32_t a;
  asm("{ .reg .u64 t; cvta.to.shared.u64 t, %1; cvt.u32.u64 %0, t; }"
      : "=r"(a) : "l"(p));
  return a;
}
__device__ __forceinline__ void cp_async16(uint32_t saddr, const void* gptr) {
  asm volatile("cp.async.cg.shared.global [%0], [%1], 16;" ::"r"(saddr),
               "l"(gptr)
               : "memory");
}
#define CP_COMMIT() asm volatile("cp.async.commit_group;" ::: "memory")
#define CP_WAIT(N) asm volatile("cp.async.wait_group %0;" ::"n"(N) : "memory")

__device__ __forceinline__ void ldsm_x4(uint32_t* d, uint32_t addr) {
  asm volatile("ldmatrix.sync.aligned.m8n8.x4.shared.b16 {%0,%1,%2,%3},[%4];"
               : "=r"(d[0]), "=r"(d[1]), "=r"(d[2]), "=r"(d[3])
               : "r"(addr));
}
__device__ __forceinline__ void ldsm_x2(uint32_t* d, uint32_t addr) {
  asm volatile("ldmatrix.sync.aligned.m8n8.x2.shared.b16 {%0,%1},[%2];"
               : "=r"(d[0]), "=r"(d[1])
               : "r"(addr));
}
__device__ __forceinline__ void mma16816(float* c, const uint32_t* a,
                                         const uint32_t* b) {
  asm volatile(
      "mma.sync.aligned.m16n8k16.row.col.f32.bf16.bf16.f32 "
      "{%0,%1,%2,%3},{%4,%5,%6,%7},{%8,%9},{%0,%1,%2,%3};"
      : "+f"(c[0]), "+f"(c[1]), "+f"(c[2]), "+f"(c[3])
      : "r"(a[0]), "r"(a[1]), "r"(a[2]), "r"(a[3]), "r"(b[0]), "r"(b[1]));
}

// ---------------------------------------------------------------------------
// Generalized pipelined bf16-split MMA GEMM.
//   C[orow(m), n] = sum_k A(m,k)*B(n,k) (+bias[n]) (+R) (relu) -> fp32 / hi-lo
//   A [M][Kdim] hi/lo, B [N][Kdim] hi/lo (pre-transposed, K-contiguous)
//   3-term split: hi*hi + hi*lo + lo*hi
//   orow(m) = (m/rpbIn)*rpbOut + rowOff + (m%rpbIn) ; C/R row stride = cN
// Tile 128x128, BK=32, 256 thr (8 warps, warp tile 64x32), cp.async 2-stage.
// ---------------------------------------------------------------------------
#define MG_BK 32
#define MG_STRIDE 40                 /* bf16 per smem row (pad 8) -> 80B */
#define MG_ARR (128 * MG_STRIDE * 2) /* 10240 B per array */
#define MG_BUF (4 * MG_ARR)          /* 40960 B per stage */
#define MG_SMEM (2 * MG_BUF)         /* 81920 B */

__global__ __launch_bounds__(256) void mma_gemm_split(
    const __nv_bfloat16* __restrict__ Ahi, const __nv_bfloat16* __restrict__ Alo,
    const __nv_bfloat16* __restrict__ Bhi, const __nv_bfloat16* __restrict__ Blo,
    const float* __restrict__ bias, const float* __restrict__ R,
    float* __restrict__ C, __nv_bfloat16* __restrict__ Chi,
    __nv_bfloat16* __restrict__ Clo, int Kdim, int cN, int relu, int rpbIn,
    int rpbOut, int rowOff) {
  extern __shared__ char sm[];
  const uint32_t sb = smem_u32(sm);
  const int tid = threadIdx.x;
  const int lane = tid & 31, wid = tid >> 5;
  const int wm = wid & 1, wn = wid >> 1;  // 2 x 4 warp grid
  const int m0 = blockIdx.y * 128, n0 = blockIdx.x * 128;
  const int nc = Kdim / MG_BK;

  const __nv_bfloat16* gA0 = Ahi + (size_t)m0 * Kdim;
  const __nv_bfloat16* gA1 = Alo + (size_t)m0 * Kdim;
  const __nv_bfloat16* gB0 = Bhi + (size_t)n0 * Kdim;
  const __nv_bfloat16* gB1 = Blo + (size_t)n0 * Kdim;

  float acc[4][4][4];
#pragma unroll
  for (int mt = 0; mt < 4; mt++)
#pragma unroll
    for (int nt = 0; nt < 4; nt++)
#pragma unroll
      for (int j = 0; j < 4; j++) acc[mt][nt][j] = 0.f;

  const int lr = tid >> 2;  // rows 0..63 (j=0), +64 (j=1)
  const int lu = tid & 3;   // 16B unit
  auto load_chunk = [&](int c, int buf) {
    int kk = c * MG_BK;
    uint32_t base = sb + buf * MG_BUF;
#pragma unroll
    for (int j = 0; j < 2; j++) {
      int r = lr + j * 64;
      uint32_t so = r * (MG_STRIDE * 2) + lu * 16;
      size_t go = (size_t)r * Kdim + kk + lu * 8;
      cp_async16(base + 0 * MG_ARR + so, gA0 + go);
      cp_async16(base + 1 * MG_ARR + so, gA1 + go);
      cp_async16(base + 2 * MG_ARR + so, gB0 + go);
      cp_async16(base + 3 * MG_ARR + so, gB1 + go);
    }
    CP_COMMIT();
  };

  load_chunk(0, 0);

  const uint32_t aRow = (wm * 64 + (lane & 15)) * (MG_STRIDE * 2);
  const uint32_t aColB = ((lane >> 4) << 3) * 2;
  const uint32_t bRow = (wn * 32 + (lane & 7)) * (MG_STRIDE * 2);
  const uint32_t bColB = (((lane >> 3) & 1) << 3) * 2;

  for (int c = 0; c < nc; c++) {
    int buf = c & 1;
    if (c + 1 < nc) {
      load_chunk(c + 1, buf ^ 1);
      CP_WAIT(1);
    } else {
      CP_WAIT(0);
    }
    __syncthreads();
    uint32_t base = sb + buf * MG_BUF;
#pragma unroll
    for (int ks = 0; ks < 2; ks++) {
      uint32_t kb = ks * 32;
      uint32_t ah[4][4], al[4][4], bh[4][2], bl[4][2];
#pragma unroll
      for (int mt = 0; mt < 4; mt++) {
        uint32_t ad = base + aRow + mt * 16 * (MG_STRIDE * 2) + kb + aColB;
        ldsm_x4(ah[mt], ad);
        ldsm_x4(al[mt], ad + MG_ARR);
      }
#pragma unroll
      for (int nt = 0; nt < 4; nt++) {
        uint32_t bd =
            base + 2 * MG_ARR + bRow + nt * 8 * (MG_STRIDE * 2) + kb + bColB;
        ldsm_x2(bh[nt], bd);
        ldsm_x2(bl[nt], bd + MG_ARR);
      }
#pragma unroll
      for (int mt = 0; mt < 4; mt++)
#pragma unroll
        for (int nt = 0; nt < 4; nt++) {
          mma16816(acc[mt][nt], ah[mt], bh[nt]);
          mma16816(acc[mt][nt], ah[mt], bl[nt]);
          mma16816(acc[mt][nt], al[mt], bh[nt]);
        }
    }
    __syncthreads();
  }

  // epilogue
#pragma unroll
  for (int mt = 0; mt < 4; mt++) {
    int mloc = wm * 64 + mt * 16 + (lane >> 2);
#pragma unroll
    for (int half = 0; half < 2; half++) {
      int m = m0 + mloc + half * 8;
      int orow = (m / rpbIn) * rpbOut + rowOff + (m % rpbIn);
#pragma unroll
      for (int nt = 0; nt < 4; nt++) {
        int n = n0 + wn * 32 + nt * 8 + (lane & 3) * 2;
        float v0 = acc[mt][nt][half * 2 + 0];
        float v1 = acc[mt][nt][half * 2 + 1];
        if (bias != nullptr) { v0 += bias[n]; v1 += bias[n + 1]; }
        if (R != nullptr) {
          float2 rv = *(const float2*)(R + (size_t)orow * cN + n);
          v0 += rv.x; v1 += rv.y;
        }
        if (relu) { v0 = fmaxf(v0, 0.f); v1 = fmaxf(v1, 0.f); }
        if (C != nullptr)
          *(float2*)(C + (size_t)orow * cN + n) = make_float2(v0, v1);
        if (Chi != nullptr) {
          __nv_bfloat16 h0 = __float2bfloat16(v0);
          __nv_bfloat16 h1 = __float2bfloat16(v1);
          *(__nv_bfloat162*)(Chi + (size_t)orow * cN + n) =
              __nv_bfloat162(h0, h1);
          *(__nv_bfloat162*)(Clo + (size_t)orow * cN + n) = __nv_bfloat162(
              __float2bfloat16(v0 - __bfloat162float(h0)),
              __float2bfloat16(v1 - __bfloat162float(h1)));
        }
      }
    }
  }
}

// ---------------------------------------------------------------------------
// LN (no affine) + bf16 hi/lo split, rows of length cD
// ---------------------------------------------------------------------------
__global__ void ln_split_kernel(const float* __restrict__ x,
                                __nv_bfloat16* __restrict__ hi,
                                __nv_bfloat16* __restrict__ lo) {
  int row = blockIdx.x;
  const float* xr = x + (size_t)row * cD;
  float s = 0.f, s2 = 0.f;
  for (int c = threadIdx.x; c < cD; c += 256) {
    float v = xr[c];
    s += v; s2 += v * v;
  }
  __shared__ float sh[64];
  for (int o = 16; o; o >>= 1) {
    s += __shfl_xor_sync(~0u, s, o);
    s2 += __shfl_xor_sync(~0u, s2, o);
  }
  int w = threadIdx.x >> 5, lane = threadIdx.x & 31;
  if (lane == 0) { sh[w] = s; sh[w + 32] = s2; }
  __syncthreads();
  if (w == 0) {
    s = (lane < 8) ? sh[lane] : 0.f;
    s2 = (lane < 8) ? sh[lane + 32] : 0.f;
    for (int o = 16; o; o >>= 1) {
      s += __shfl_xor_sync(~0u, s, o);
      s2 += __shfl_xor_sync(~0u, s2, o);
    }
    if (lane == 0) { sh[0] = s; sh[1] = s2; }
  }
  __syncthreads();
  float mean = sh[0] * (1.f / cD);
  float rstd = rsqrtf(sh[1] * (1.f / cD) - mean * mean + cEPS);
  for (int c = threadIdx.x; c < cD; c += 256) {
    float v = (xr[c] - mean) * rstd;
    __nv_bfloat16 h = __float2bfloat16(v);
    hi[(size_t)row * cD + c] = h;
    lo[(size_t)row * cD + c] = __float2bfloat16(v - __bfloat162float(h));
  }
}

// ---------------------------------------------------------------------------
// Weight prep: Wt[n][k] = (g?g[k]:1)*W[k][n] bf16 hi/lo; bias[n]=sum_k b[k]W[k][n]
// W is [Kdim][Nw]; one block per n
// ---------------------------------------------------------------------------
__global__ void wprep_kernel(const float* __restrict__ W,
                             const float* __restrict__ g,
                             const float* __restrict__ b,
                             __nv_bfloat16* __restrict__ Whi,
                             __nv_bfloat16* __restrict__ Wlo,
                             float* __restrict__ bias, int Kdim, int Nw) {
  int n = blockIdx.x;
  float bs = 0.f;
  for (int k = threadIdx.x; k < Kdim; k += 256) {
    float w = W[(size_t)k * Nw + n];
    float v = (g != nullptr) ? g[k] * w : w;
    __nv_bfloat16 h = __float2bfloat16(v);
    Whi[(size_t)n * Kdim + k] = h;
    Wlo[(size_t)n * Kdim + k] = __float2bfloat16(v - __bfloat162float(h));
    if (b != nullptr) bs += b[k] * w;
  }
  if (bias != nullptr) {
    __shared__ float sh[8];
    for (int o = 16; o; o >>= 1) bs += __shfl_xor_sync(~0u, bs, o);
    int w8 = threadIdx.x >> 5, lane = threadIdx.x & 31;
    if (lane == 0) sh[w8] = bs;
    __syncthreads();
    if (threadIdx.x == 0) {
      float t = 0.f;
      for (int i = 0; i < 8; i++) t += sh[i];
      bias[n] = t;
    }
  }
}

// ---------------------------------------------------------------------------
// Broadcast latents -> (B, L, D)
// ---------------------------------------------------------------------------
__global__ void bcast_latents_kernel(const float* __restrict__ lat,
                                     float* __restrict__ out) {
  int idx = blockIdx.x * 256 + threadIdx.x;
  out[idx] = lat[idx % (cL * cD)];
}

// ---------------------------------------------------------------------------
// Final LayerNorm with affine (block per row)
// ---------------------------------------------------------------------------
__global__ void ln_rows_kernel(const float* __restrict__ x,
                               float* __restrict__ y,
                               const float* __restrict__ g,
                               const float* __restrict__ b) {
  int row = blockIdx.x;
  const float* xr = x + (size_t)row * cD;
  float* yr = y + (size_t)row * cD;
  float s = 0.f, s2 = 0.f;
  for (int c = threadIdx.x; c < cD; c += 256) {
    float v = xr[c];
    s += v; s2 += v * v;
  }
  __shared__ float sh[64];
  for (int o = 16; o; o >>= 1) {
    s += __shfl_xor_sync(~0u, s, o);
    s2 += __shfl_xor_sync(~0u, s2, o);
  }
  int w = threadIdx.x >> 5, lane = threadIdx.x & 31;
  if (lane == 0) { sh[w] = s; sh[w + 32] = s2; }
  __syncthreads();
  if (w == 0) {
    s = (lane < 8) ? sh[lane] : 0.f;
    s2 = (lane < 8) ? sh[lane + 32] : 0.f;
    for (int o = 16; o; o >>= 1) {
      s += __shfl_xor_sync(~0u, s, o);
      s2 += __shfl_xor_sync(~0u, s2, o);
    }
    if (lane == 0) { sh[0] = s; sh[1] = s2; }
  }
  __syncthreads();
  float mean = sh[0] * (1.f / cD);
  float rstd = rsqrtf(sh[1] * (1.f / cD) - mean * mean + cEPS);
  for (int c = threadIdx.x; c < cD; c += 256)
    yr[c] = (xr[c] - mean) * rstd * g[c] + b[c];
}

// ---------------------------------------------------------------------------
// Per-head LN over 96-element subrows (warp per row, in place)
// ---------------------------------------------------------------------------
__global__ void ln_head_kernel(float* x, const float* __restrict__ g,
                               const float* __restrict__ b, int nrows) {
  int r = blockIdx.x * 4 + (threadIdx.x >> 5);
  if (r >= nrows) return;
  int lane = threadIdx.x & 31;
  float* xr = x + (size_t)r * cHD;
  float v0 = xr[lane], v1 = xr[lane + 32], v2 = xr[lane + 64];
  float s = v0 + v1 + v2;
  float s2 = v0 * v0 + v1 * v1 + v2 * v2;
  for (int o = 16; o; o >>= 1) {
    s += __shfl_xor_sync(~0u, s, o);
    s2 += __shfl_xor_sync(~0u, s2, o);
  }
  float mean = s * (1.f / 96.f);
  float rstd = rsqrtf(s2 * (1.f / 96.f) - mean * mean + cEPS);
  xr[lane]      = (v0 - mean) * rstd * g[lane]      + b[lane];
  xr[lane + 32] = (v1 - mean) * rstd * g[lane + 32] + b[lane + 32];
  xr[lane + 64] = (v2 - mean) * rstd * g[lane + 64] + b[lane + 64];
}

// ---------------------------------------------------------------------------
// Attention scores: Sc[bh,l,t] = scale * q.k
// ---------------------------------------------------------------------------
#define SC_SMEM (2 * 64 * 97 * 4)
__global__ __launch_bounds__(256) void attn_scores_kernel(
    const float* __restrict__ Q, const float* __restrict__ K,
    float* __restrict__ Sc) {
  extern __shared__ float smf[];
  float(*qs)[97] = (float(*)[97])smf;
  float(*ks)[97] = (float(*)[97])(smf + 64 * 97);
  int bh = blockIdx.y;
  int b = bh >> 4, h = bh & 15;
  int t0 = blockIdx.x * 64;
  const float* Qb = Q + (size_t)(b * cL) * cHHD + h * cHD;
  const float* Kb = K + (size_t)(b * cT + t0) * cHHD + h * cHD;
  for (int idx = threadIdx.x; idx < 64 * 96; idx += 256) {
    int r = idx / 96, c = idx % 96;
    qs[r][c] = Qb[(size_t)r * cHHD + c];
    ks[r][c] = Kb[(size_t)r * cHHD + c];
  }
  __syncthreads();
  int lh = threadIdx.x >> 4, th = threadIdx.x & 15;
  float acc[4][4];
#pragma unroll
  for (int i = 0; i < 4; i++)
#pragma unroll
    for (int j = 0; j < 4; j++) acc[i][j] = 0.f;
#pragma unroll 4
  for (int d = 0; d < 96; d++) {
    float qv[4], kv[4];
#pragma unroll
    for (int i = 0; i < 4; i++) {
      qv[i] = qs[lh * 4 + i][d];
      kv[i] = ks[th * 4 + i][d];
    }
#pragma unroll
    for (int i = 0; i < 4; i++)
#pragma unroll
      for (int j = 0; j < 4; j++) acc[i][j] += qv[i] * kv[j];
  }
  const float scale = 0.102062072615966f;
#pragma unroll
  for (int i = 0; i < 4; i++)
#pragma unroll
    for (int j = 0; j < 4; j++)
      Sc[((size_t)bh * cL + lh * 4 + i) * cT + t0 + th * 4 + j] =
          acc[i][j] * scale;
}

// ---------------------------------------------------------------------------
// Row softmax over 2368 (block per row, in place)
// ---------------------------------------------------------------------------
__global__ void softmax_rows_kernel(float* Sc) {
  float* x = Sc + (size_t)blockIdx.x * cT;
  int tid = threadIdx.x;
  __shared__ float sh[32];
  __shared__ float bc;
  float m = -1e30f;
  for (int c = tid; c < cT; c += 256) m = fmaxf(m, x[c]);
  for (int o = 16; o; o >>= 1) m = fmaxf(m, __shfl_xor_sync(~0u, m, o));
  int w = tid >> 5, lane = tid & 31;
  if (lane == 0) sh[w] = m;
  __syncthreads();
  if (w == 0) {
    m = (lane < 8) ? sh[lane] : -1e30f;
    for (int o = 16; o; o >>= 1) m = fmaxf(m, __shfl_xor_sync(~0u, m, o));
    if (lane == 0) bc = m;
  }
  __syncthreads();
  m = bc;
  float s = 0.f;
  for (int c = tid; c < cT; c += 256) {
    float e = __expf(x[c] - m);
    x[c] = e;
    s += e;
  }
  for (int o = 16; o; o >>= 1) s += __shfl_xor_sync(~0u, s, o);
  __syncthreads();
  if (lane == 0) sh[w] = s;
  __syncthreads();
  if (w == 0) {
    s = (lane < 8) ? sh[lane] : 0.f;
    for (int o = 16; o; o >>= 1) s += __shfl_xor_sync(~0u, s, o);
    if (lane == 0) bc = 1.f / s;
  }
  __syncthreads();
  float inv = bc;
  for (int c = tid; c < cT; c += 256) x[c] *= inv;
}

// ---------------------------------------------------------------------------
// attn @ V -> att output as bf16 hi/lo (consumed by the Wo MMA GEMM)
// ---------------------------------------------------------------------------
__global__ __launch_bounds__(256) void attn_av_kernel(
    const float* __restrict__ P, const float* __restrict__ V,
    __nv_bfloat16* __restrict__ Ohi, __nv_bfloat16* __restrict__ Olo) {
  __shared__ float ps[64][65];
  __shared__ float vs[64][97];
  int bh = blockIdx.x;
  int b = bh >> 4, h = bh & 15;
  int lh = threadIdx.x >> 4, dh = threadIdx.x & 15;
  float acc[4][6];
#pragma unroll
  for (int i = 0; i < 4; i++)
#pragma unroll
    for (int j = 0; j < 6; j++) acc[i][j] = 0.f;
  const float* Pb = P + (size_t)bh * cL * cT;
  const float* Vb = V + (size_t)b * cT * cHHD + h * cHD;
  for (int ct = 0; ct < 37; ct++) {
    int t0 = ct * 64;
    for (int idx = threadIdx.x; idx < 64 * 64; idx += 256) {
      int r = idx >> 6, c = idx & 63;
      ps[r][c] = Pb[(size_t)r * cT + t0 + c];
    }
    for (int idx = threadIdx.x; idx < 64 * 96; idx += 256) {
      int r = idx / 96, c = idx % 96;
      vs[r][c] = Vb[(size_t)(t0 + r) * cHHD + c];
    }
    __syncthreads();
#pragma unroll 4
    for (int tt = 0; tt < 64; tt++) {
      float pv[4], vv[6];
#pragma unroll
      for (int i = 0; i < 4; i++) pv[i] = ps[lh * 4 + i][tt];
#pragma unroll
      for (int j = 0; j < 6; j++) vv[j] = vs[tt][dh * 6 + j];
#pragma unroll
      for (int i = 0; i < 4; i++)
#pragma unroll
        for (int j = 0; j < 6; j++) acc[i][j] += pv[i] * vv[j];
    }
    __syncthreads();
  }
#pragma unroll
  for (int i = 0; i < 4; i++)
#pragma unroll
    for (int j = 0; j < 6; j++) {
      size_t o = (size_t)(b * cL + lh * 4 + i) * cHHD + h * cHD + dh * 6 + j;
      float v = acc[i][j];
      __nv_bfloat16 hh = __float2bfloat16(v);
      Ohi[o] = hh;
      Olo[o] = __float2bfloat16(v - __bfloat162float(hh));
    }
}

// ---------------------------------------------------------------------------
// Host orchestration
// ---------------------------------------------------------------------------
extern "C" void kernel_launch(void* const* d_in, const int* in_sizes, int n_in,
                              void* d_out, int out_size) {
  (void)in_sizes; (void)n_in; (void)out_size;
  const float* context = (const float*)d_in[0];
  const float* latents = (const float*)d_in[1];
  const float* ctx_g = (const float*)d_in[2];
  const float* ctx_b = (const float*)d_in[3];
  const float* lat_g = (const float*)d_in[4];
  const float* lat_b = (const float*)d_in[5];
  const float* q_g = (const float*)d_in[6];
  const float* q_b = (const float*)d_in[7];
  const float* k_g = (const float*)d_in[8];
  const float* k_b = (const float*)d_in[9];
  const float* Wq = (const float*)d_in[10];
  const float* Wk = (const float*)d_in[11];
  const float* Wv = (const float*)d_in[12];
  const float* Wo = (const float*)d_in[13];
  const float* mlp_g = (const float*)d_in[14];
  const float* mlp_b = (const float*)d_in[15];
  const float* Wfc = (const float*)d_in[16];
  const float* Wcp = (const float*)d_in[17];
  const float* f_g = (const float*)d_in[18];
  const float* f_b = (const float*)d_in[19];
  float* out = (float*)d_out;

#define SYM(var, sym) cudaGetSymbolAddress((void**)&var, sym)
  __nv_bfloat16 *ctxhi, *ctxlo, *lnhi, *lnlo, *atthi, *attlo, *mlphi, *mlplo;
  __nv_bfloat16 *wqh, *wql, *wkch, *wkcl, *wklh, *wkll, *wvch, *wvcl, *wvlh,
      *wvll, *woh, *wol, *wfch, *wfcl, *wcph, *wcpl;
  float *bQ, *bKc, *bKl, *bVc, *bVl, *bFc;
  float *lat, *Qp, *Kp, *Vp, *Scp;
  SYM(ctxhi, g_ctx_hi); SYM(ctxlo, g_ctx_lo);
  SYM(lnhi, g_latln_hi); SYM(lnlo, g_latln_lo);
  SYM(atthi, g_att_hi); SYM(attlo, g_att_lo);
  SYM(mlphi, g_mlp_hi); SYM(mlplo, g_mlp_lo);
  SYM(wqh, g_wq_hi); SYM(wql, g_wq_lo);
  SYM(wkch, g_wkc_hi); SYM(wkcl, g_wkc_lo);
  SYM(wklh, g_wkl_hi); SYM(wkll, g_wkl_lo);
  SYM(wvch, g_wvc_hi); SYM(wvcl, g_wvc_lo);
  SYM(wvlh, g_wvl_hi); SYM(wvll, g_wvl_lo);
  SYM(woh, g_wo_hi); SYM(wol, g_wo_lo);
  SYM(wfch, g_wfc_hi); SYM(wfcl, g_wfc_lo);
  SYM(wcph, g_wcp_hi); SYM(wcpl, g_wcp_lo);
  SYM(bQ, g_biasQ); SYM(bKc, g_biasKc); SYM(bKl, g_biasKl);
  SYM(bVc, g_biasVc); SYM(bVl, g_biasVl); SYM(bFc, g_biasFc);
  SYM(lat, g_lat); SYM(Qp, g_Q); SYM(Kp, g_K); SYM(Vp, g_V); SYM(Scp, g_scores);
#undef SYM

  cudaFuncSetAttribute(attn_scores_kernel,
                       cudaFuncAttributeMaxDynamicSharedMemorySize, SC_SMEM);
  cudaFuncSetAttribute(mma_gemm_split,
                       cudaFuncAttributeMaxDynamicSharedMemorySize, MG_SMEM);

  // once: LN(context) -> bf16 hi/lo ; latent broadcast
  ln_split_kernel<<<cMCTX, 256>>>(context, ctxhi, ctxlo);
  bcast_latents_kernel<<<(cML * cD) / 256, 256>>>(latents, lat);

  auto mma = [&](const __nv_bfloat16* Ah, const __nv_bfloat16* Al,
                 const __nv_bfloat16* Bh, const __nv_bfloat16* Bl,
                 const float* bias, const float* R, float* C,
                 __nv_bfloat16* Ch, __nv_bfloat16* Cl, int M, int N, int Kd,
                 int relu, int rpbIn, int rpbOut, int rowOff) {
    dim3 grid(N / 128, M / 128);
    mma_gemm_split<<<grid, 256, MG_SMEM>>>(Ah, Al, Bh, Bl, bias, R, C, Ch, Cl,
                                           Kd, N, relu, rpbIn, rpbOut, rowOff);
  };

  for (int i = 0; i < cDEPTH; i++) {
    const float* Wq_i = Wq + (size_t)i * cD * cHHD;
    const float* Wk_i = Wk + (size_t)i * cD * cHHD;
    const float* Wv_i = Wv + (size_t)i * cD * cHHD;
    const float* Wo_i = Wo + (size_t)i * cHHD * cD;
    const float* Wfc_i = Wfc + (size_t)i * cD * cI;
    const float* Wcp_i = Wcp + (size_t)i * cI * cD;
    const float* lg = lat_g + i * cD;
    const float* lb = lat_b + i * cD;

    // LN(latents) -> normalized hi/lo (affine folded into weights below)
    ln_split_kernel<<<cML, 256>>>(lat, lnhi, lnlo);

    // weight preps (transposed hi/lo + rank-1 bias)
    wprep_kernel<<<cHHD, 256>>>(Wq_i, lg, lb, wqh, wql, bQ, cD, cHHD);
    wprep_kernel<<<cHHD, 256>>>(Wk_i, ctx_g + i * cD, ctx_b + i * cD, wkch,
                                wkcl, bKc, cD, cHHD);
    wprep_kernel<<<cHHD, 256>>>(Wk_i, lg, lb, wklh, wkll, bKl, cD, cHHD);
    wprep_kernel<<<cHHD, 256>>>(Wv_i, ctx_g + i * cD, ctx_b + i * cD, wvch,
                                wvcl, bVc, cD, cHHD);
    wprep_kernel<<<cHHD, 256>>>(Wv_i, lg, lb, wvlh, wvll, bVl, cD, cHHD);

    // Q = l̂@(g⊙Wq)+b·Wq  (fp32 out for per-head LN)
    mma(lnhi, lnlo, wqh, wql, bQ, nullptr, Qp, nullptr, nullptr, cML, cHHD, cD,
        0, cML, cML, 0);
    // K,V: context rows (ctx-folded) + latent rows (lat-folded) into [S+L]
    mma(ctxhi, ctxlo, wkch, wkcl, bKc, nullptr, Kp, nullptr, nullptr, cMCTX,
        cHHD, cD, 0, cS, cT, 0);
    mma(lnhi, lnlo, wklh, wkll, bKl, nullptr, Kp, nullptr, nullptr, cML, cHHD,
        cD, 0, cL, cT, cS);
    mma(ctxhi, ctxlo, wvch, wvcl, bVc, nullptr, Vp, nullptr, nullptr, cMCTX,
        cHHD, cD, 0, cS, cT, 0);
    mma(lnhi, lnlo, wvlh, wvll, bVl, nullptr, Vp, nullptr, nullptr, cML, cHHD,
        cD, 0, cL, cT, cS);

    // per-head q/k LN
    ln_head_kernel<<<(cML * cH) / 4, 128>>>(Qp, q_g + i * cHD, q_b + i * cHD,
                                            cML * cH);
    ln_head_kernel<<<(cB * cT * cH) / 4, 128>>>(Kp, k_g + i * cHD,
                                                k_b + i * cHD, cB * cT * cH);

    // attention (fp32), AV emits hi/lo for the Wo GEMM
    attn_scores_kernel<<<dim3(cT / 64, cB * cH), 256, SC_SMEM>>>(Qp, Kp, Scp);
    softmax_rows_kernel<<<cB * cH * cL, 256>>>(Scp);
    attn_av_kernel<<<cB * cH, 256>>>(Scp, Vp, atthi, attlo);

    // lat = att @ Wo + lat
    wprep_kernel<<<cD, 256>>>(Wo_i, nullptr, nullptr, woh, wol, nullptr, cHHD,
                              cD);
    mma(atthi, attlo, woh, wol, nullptr, lat, lat, nullptr, nullptr, cML, cD,
        cHHD, 0, cML, cML, 0);

    // MLP: h = relu(m̂@(g⊙Wfc)+b·Wfc) -> hi/lo ; lat += h @ Wcp
    ln_split_kernel<<<cML, 256>>>(lat, lnhi, lnlo);
    wprep_kernel<<<cI, 256>>>(Wfc_i, mlp_g + i * cD, mlp_b + i * cD, wfch, wfcl,
                              bFc, cD, cI);
    mma(lnhi, lnlo, wfch, wfcl, bFc, nullptr, nullptr, mlphi, mlplo, cML, cI,
        cD, 1, cML, cML, 0);
    wprep_kernel<<<cD, 256>>>(Wcp_i, nullptr, nullptr, wcph, wcpl, nullptr, cI,
                              cD);
    mma(mlphi, mlplo, wcph, wcpl, nullptr, lat, lat, nullptr, nullptr, cML, cD,
        cI, 0, cML, cML, 0);
  }

  ln_rows_kernel<<<cML, 256>>>(lat, out, f_g, f_b);
}

// round 5
// speedup vs baseline: 2.1773x; 1.0685x over previous
#include <cuda_runtime.h>
#include <cuda_bf16.h>
#include <cstdint>
#include <cstddef>

// ---------------------------------------------------------------------------
// Problem constants
// ---------------------------------------------------------------------------
#define cB 32
#define cS 2304
#define cD 1280
#define cDEPTH 6
#define cH 16
#define cHD 96
#define cL 64
#define cI 5120
#define cT (cS + cL)      /* 2368 */
#define cHHD (cH * cHD)   /* 1536 */
#define cEPS 1e-5f
#define cMCTX (cB * cS)   /* 73728 ctx rows */
#define cML (cB * cL)     /* 2048 latent rows */

typedef __nv_bfloat16 bf16;

// ---------------------------------------------------------------------------
// Scratch (device globals: allocation-free rule)
// ---------------------------------------------------------------------------
__device__ bf16 g_ctx_hi[(size_t)cMCTX * cD];
__device__ bf16 g_ctx_lo[(size_t)cMCTX * cD];
__device__ bf16 g_latln_hi[cML * cD];
__device__ bf16 g_latln_lo[cML * cD];
__device__ bf16 g_att_hi[cML * cHHD];
__device__ bf16 g_att_lo[cML * cHHD];
__device__ bf16 g_mlp_hi[(size_t)cML * cI];
__device__ bf16 g_mlp_lo[(size_t)cML * cI];
// attention operands (hi/lo)
__device__ bf16 g_Q_hi[cML * cHHD], g_Q_lo[cML * cHHD];
__device__ bf16 g_K_hi[(size_t)cB * cT * cHHD], g_K_lo[(size_t)cB * cT * cHHD];
__device__ bf16 g_V_hi[(size_t)cB * cT * cHHD], g_V_lo[(size_t)cB * cT * cHHD];
__device__ bf16 g_P_hi[(size_t)cB * cH * cL * cT];
__device__ bf16 g_P_lo[(size_t)cB * cH * cL * cT];
// transposed (folded) weights, hi/lo
__device__ bf16 g_wq_hi[cHHD * cD],  g_wq_lo[cHHD * cD];
__device__ bf16 g_wkc_hi[cHHD * cD], g_wkc_lo[cHHD * cD];
__device__ bf16 g_wkl_hi[cHHD * cD], g_wkl_lo[cHHD * cD];
__device__ bf16 g_wvc_hi[cHHD * cD], g_wvc_lo[cHHD * cD];
__device__ bf16 g_wvl_hi[cHHD * cD], g_wvl_lo[cHHD * cD];
__device__ bf16 g_wo_hi[cD * cHHD],  g_wo_lo[cD * cHHD];
__device__ bf16 g_wfc_hi[(size_t)cI * cD], g_wfc_lo[(size_t)cI * cD];
__device__ bf16 g_wcp_hi[(size_t)cD * cI], g_wcp_lo[(size_t)cD * cI];
__device__ float g_biasQ[cHHD], g_biasKc[cHHD], g_biasKl[cHHD];
__device__ float g_biasVc[cHHD], g_biasVl[cHHD], g_biasFc[cI];
__device__ float g_lat[cML * cD];
__device__ float g_Q[cML * cHHD];
__device__ float g_K[(size_t)cB * cT * cHHD];
__device__ float g_scores[(size_t)cB * cH * cL * cT];

// ---------------------------------------------------------------------------
// MMA helpers (base-PTX: ldmatrix + mma.sync, sm_80+)
// ---------------------------------------------------------------------------
__device__ __forceinline__ uint32_t smem_u32(const void* p) {
  uint32_t a;
  asm("{ .reg .u64 t; cvta.to.shared.u64 t, %1; cvt.u32.u64 %0, t; }"
      : "=r"(a) : "l"(p));
  return a;
}
__device__ __forceinline__ void cp_async16(uint32_t saddr, const void* gptr) {
  asm volatile("cp.async.cg.shared.global [%0], [%1], 16;" ::"r"(saddr),
               "l"(gptr)
               : "memory");
}
#define CP_COMMIT() asm volatile("cp.async.commit_group;" ::: "memory")
#define CP_WAIT(N) asm volatile("cp.async.wait_group %0;" ::"n"(N) : "memory")

__device__ __forceinline__ void ldsm_x4(uint32_t* d, uint32_t addr) {
  asm volatile("ldmatrix.sync.aligned.m8n8.x4.shared.b16 {%0,%1,%2,%3},[%4];"
               : "=r"(d[0]), "=r"(d[1]), "=r"(d[2]), "=r"(d[3])
               : "r"(addr));
}
__device__ __forceinline__ void ldsm_x2(uint32_t* d, uint32_t addr) {
  asm volatile("ldmatrix.sync.aligned.m8n8.x2.shared.b16 {%0,%1},[%2];"
               : "=r"(d[0]), "=r"(d[1])
               : "r"(addr));
}
__device__ __forceinline__ void ldsm_x2_trans(uint32_t* d, uint32_t addr) {
  asm volatile("ldmatrix.sync.aligned.m8n8.x2.trans.shared.b16 {%0,%1},[%2];"
               : "=r"(d[0]), "=r"(d[1])
               : "r"(addr));
}
__device__ __forceinline__ void mma16816(float* c, const uint32_t* a,
                                         const uint32_t* b) {
  asm volatile(
      "mma.sync.aligned.m16n8k16.row.col.f32.bf16.bf16.f32 "
      "{%0,%1,%2,%3},{%4,%5,%6,%7},{%8,%9},{%0,%1,%2,%3};"
      : "+f"(c[0]), "+f"(c[1]), "+f"(c[2]), "+f"(c[3])
      : "r"(a[0]), "r"(a[1]), "r"(a[2]), "r"(a[3]), "r"(b[0]), "r"(b[1]));
}

// ---------------------------------------------------------------------------
// Generalized pipelined bf16-split MMA GEMM (unchanged from round 4).
// ---------------------------------------------------------------------------
#define MG_BK 32
#define MG_STRIDE 40
#define MG_ARR (128 * MG_STRIDE * 2)
#define MG_BUF (4 * MG_ARR)
#define MG_SMEM (2 * MG_BUF)

__global__ __launch_bounds__(256) void mma_gemm_split(
    const bf16* __restrict__ Ahi, const bf16* __restrict__ Alo,
    const bf16* __restrict__ Bhi, const bf16* __restrict__ Blo,
    const float* __restrict__ bias, const float* __restrict__ R,
    float* __restrict__ C, bf16* __restrict__ Chi, bf16* __restrict__ Clo,
    int Kdim, int cN, int relu, int rpbIn, int rpbOut, int rowOff) {
  extern __shared__ char sm[];
  const uint32_t sb = smem_u32(sm);
  const int tid = threadIdx.x;
  const int lane = tid & 31, wid = tid >> 5;
  const int wm = wid & 1, wn = wid >> 1;
  const int m0 = blockIdx.y * 128, n0 = blockIdx.x * 128;
  const int nc = Kdim / MG_BK;

  const bf16* gA0 = Ahi + (size_t)m0 * Kdim;
  const bf16* gA1 = Alo + (size_t)m0 * Kdim;
  const bf16* gB0 = Bhi + (size_t)n0 * Kdim;
  const bf16* gB1 = Blo + (size_t)n0 * Kdim;

  float acc[4][4][4];
#pragma unroll
  for (int mt = 0; mt < 4; mt++)
#pragma unroll
    for (int nt = 0; nt < 4; nt++)
#pragma unroll
      for (int j = 0; j < 4; j++) acc[mt][nt][j] = 0.f;

  const int lr = tid >> 2;
  const int lu = tid & 3;
  auto load_chunk = [&](int c, int buf) {
    int kk = c * MG_BK;
    uint32_t base = sb + buf * MG_BUF;
#pragma unroll
    for (int j = 0; j < 2; j++) {
      int r = lr + j * 64;
      uint32_t so = r * (MG_STRIDE * 2) + lu * 16;
      size_t go = (size_t)r * Kdim + kk + lu * 8;
      cp_async16(base + 0 * MG_ARR + so, gA0 + go);
      cp_async16(base + 1 * MG_ARR + so, gA1 + go);
      cp_async16(base + 2 * MG_ARR + so, gB0 + go);
      cp_async16(base + 3 * MG_ARR + so, gB1 + go);
    }
    CP_COMMIT();
  };

  load_chunk(0, 0);

  const uint32_t aRow = (wm * 64 + (lane & 15)) * (MG_STRIDE * 2);
  const uint32_t aColB = ((lane >> 4) << 3) * 2;
  const uint32_t bRow = (wn * 32 + (lane & 7)) * (MG_STRIDE * 2);
  const uint32_t bColB = (((lane >> 3) & 1) << 3) * 2;

  for (int c = 0; c < nc; c++) {
    int buf = c & 1;
    if (c + 1 < nc) {
      load_chunk(c + 1, buf ^ 1);
      CP_WAIT(1);
    } else {
      CP_WAIT(0);
    }
    __syncthreads();
    uint32_t base = sb + buf * MG_BUF;
#pragma unroll
    for (int ks = 0; ks < 2; ks++) {
      uint32_t kb = ks * 32;
      uint32_t ah[4][4], al[4][4], bh[4][2], bl[4][2];
#pragma unroll
      for (int mt = 0; mt < 4; mt++) {
        uint32_t ad = base + aRow + mt * 16 * (MG_STRIDE * 2) + kb + aColB;
        ldsm_x4(ah[mt], ad);
        ldsm_x4(al[mt], ad + MG_ARR);
      }
#pragma unroll
      for (int nt = 0; nt < 4; nt++) {
        uint32_t bd =
            base + 2 * MG_ARR + bRow + nt * 8 * (MG_STRIDE * 2) + kb + bColB;
        ldsm_x2(bh[nt], bd);
        ldsm_x2(bl[nt], bd + MG_ARR);
      }
#pragma unroll
      for (int mt = 0; mt < 4; mt++)
#pragma unroll
        for (int nt = 0; nt < 4; nt++) {
          mma16816(acc[mt][nt], ah[mt], bh[nt]);
          mma16816(acc[mt][nt], ah[mt], bl[nt]);
          mma16816(acc[mt][nt], al[mt], bh[nt]);
        }
    }
    __syncthreads();
  }

#pragma unroll
  for (int mt = 0; mt < 4; mt++) {
    int mloc = wm * 64 + mt * 16 + (lane >> 2);
#pragma unroll
    for (int half = 0; half < 2; half++) {
      int m = m0 + mloc + half * 8;
      int orow = (m / rpbIn) * rpbOut + rowOff + (m % rpbIn);
#pragma unroll
      for (int nt = 0; nt < 4; nt++) {
        int n = n0 + wn * 32 + nt * 8 + (lane & 3) * 2;
        float v0 = acc[mt][nt][half * 2 + 0];
        float v1 = acc[mt][nt][half * 2 + 1];
        if (bias != nullptr) { v0 += bias[n]; v1 += bias[n + 1]; }
        if (R != nullptr) {
          float2 rv = *(const float2*)(R + (size_t)orow * cN + n);
          v0 += rv.x; v1 += rv.y;
        }
        if (relu) { v0 = fmaxf(v0, 0.f); v1 = fmaxf(v1, 0.f); }
        if (C != nullptr)
          *(float2*)(C + (size_t)orow * cN + n) = make_float2(v0, v1);
        if (Chi != nullptr) {
          bf16 h0 = __float2bfloat16(v0);
          bf16 h1 = __float2bfloat16(v1);
          *(__nv_bfloat162*)(Chi + (size_t)orow * cN + n) =
              __nv_bfloat162(h0, h1);
          *(__nv_bfloat162*)(Clo + (size_t)orow * cN + n) = __nv_bfloat162(
              __float2bfloat16(v0 - __bfloat162float(h0)),
              __float2bfloat16(v1 - __bfloat162float(h1)));
        }
      }
    }
  }
}

// ---------------------------------------------------------------------------
// Attention scores on MMA: Sc[bh,l,t0+0:64] = scale * Q(hi/lo) . K(hi/lo)
// grid (37, 512), 256 thr. smem: Qh,Ql,Kh,Kl [64][104] bf16.
// ---------------------------------------------------------------------------
#define SCM_STRIDE 104
#define SCM_ARR (64 * SCM_STRIDE * 2) /* 13312 */
#define SCM_SMEM (4 * SCM_ARR)        /* 53248 */
__global__ __launch_bounds__(256) void attn_scores_mma(
    const bf16* __restrict__ Qh, const bf16* __restrict__ Ql,
    const bf16* __restrict__ Kh, const bf16* __restrict__ Kl,
    float* __restrict__ Sc) {
  extern __shared__ char sm[];
  const uint32_t sb = smem_u32(sm);
  const int tid = threadIdx.x, lane = tid & 31, wid = tid >> 5;
  const int bh = blockIdx.y, b = bh >> 4, h = bh & 15;
  const int t0 = blockIdx.x * 64;

#pragma unroll
  for (int it = 0; it < 3; it++) {
    int e = tid + it * 256;  // 768 units per array
    int r = e / 12, u = e % 12;
    uint32_t so = r * (SCM_STRIDE * 2) + u * 16;
    size_t qo = (size_t)(b * cL + r) * cHHD + h * cHD + u * 8;
    size_t ko = (size_t)(b * cT + t0 + r) * cHHD + h * cHD + u * 8;
    *(uint4*)(sm + 0 * SCM_ARR + so) = *(const uint4*)(Qh + qo);
    *(uint4*)(sm + 1 * SCM_ARR + so) = *(const uint4*)(Ql + qo);
    *(uint4*)(sm + 2 * SCM_ARR + so) = *(const uint4*)(Kh + ko);
    *(uint4*)(sm + 3 * SCM_ARR + so) = *(const uint4*)(Kl + ko);
  }
  __syncthreads();

  const int wm = wid & 1, wn = wid >> 1;  // 2 x 4
  float acc[2][2][4];
#pragma unroll
  for (int mt = 0; mt < 2; mt++)
#pragma unroll
    for (int nt = 0; nt < 2; nt++)
#pragma unroll
      for (int j = 0; j < 4; j++) acc[mt][nt][j] = 0.f;

#pragma unroll
  for (int ks = 0; ks < 6; ks++) {
    uint32_t kb = ks * 32;  // 16 bf16 = 32B
    uint32_t ah[2][4], al[2][4], bh2[2][2], bl2[2][2];
#pragma unroll
    for (int mt = 0; mt < 2; mt++) {
      uint32_t ad = sb + (wm * 32 + mt * 16 + (lane & 15)) * (SCM_STRIDE * 2) +
                    kb + (lane >> 4) * 16;
      ldsm_x4(ah[mt], ad);
      ldsm_x4(al[mt], ad + SCM_ARR);
    }
#pragma unroll
    for (int nt = 0; nt < 2; nt++) {
      uint32_t bd = sb + 2 * SCM_ARR +
                    (wn * 16 + nt * 8 + (lane & 7)) * (SCM_STRIDE * 2) + kb +
                    ((lane >> 3) & 1) * 16;
      ldsm_x2(bh2[nt], bd);
      ldsm_x2(bl2[nt], bd + SCM_ARR);
    }
#pragma unroll
    for (int mt = 0; mt < 2; mt++)
#pragma unroll
      for (int nt = 0; nt < 2; nt++) {
        mma16816(acc[mt][nt], ah[mt], bh2[nt]);
        mma16816(acc[mt][nt], ah[mt], bl2[nt]);
        mma16816(acc[mt][nt], al[mt], bh2[nt]);
      }
  }

  const float scale = 0.102062072615966f;  // 96^-0.5
#pragma unroll
  for (int mt = 0; mt < 2; mt++)
#pragma unroll
    for (int half = 0; half < 2; half++) {
      int row = wm * 32 + mt * 16 + (lane >> 2) + half * 8;
#pragma unroll
      for (int nt = 0; nt < 2; nt++) {
        int col = t0 + wn * 16 + nt * 8 + (lane & 3) * 2;
        *(float2*)(Sc + ((size_t)bh * cL + row) * cT + col) =
            make_float2(acc[mt][nt][half * 2] * scale,
                        acc[mt][nt][half * 2 + 1] * scale);
      }
    }
}

// ---------------------------------------------------------------------------
// Row softmax over 2368; emits P as bf16 hi/lo. Sc used as exp scratch.
// ---------------------------------------------------------------------------
__global__ void softmax_split_kernel(float* __restrict__ Sc,
                                     bf16* __restrict__ Ph,
                                     bf16* __restrict__ Pl) {
  float* x = Sc + (size_t)blockIdx.x * cT;
  bf16* ph = Ph + (size_t)blockIdx.x * cT;
  bf16* pl = Pl + (size_t)blockIdx.x * cT;
  int tid = threadIdx.x;
  __shared__ float sh[32];
  __shared__ float bc;
  float m = -1e30f;
  for (int c = tid; c < cT; c += 256) m = fmaxf(m, x[c]);
  for (int o = 16; o; o >>= 1) m = fmaxf(m, __shfl_xor_sync(~0u, m, o));
  int w = tid >> 5, lane = tid & 31;
  if (lane == 0) sh[w] = m;
  __syncthreads();
  if (w == 0) {
    m = (lane < 8) ? sh[lane] : -1e30f;
    for (int o = 16; o; o >>= 1) m = fmaxf(m, __shfl_xor_sync(~0u, m, o));
    if (lane == 0) bc = m;
  }
  __syncthreads();
  m = bc;
  float s = 0.f;
  for (int c = tid; c < cT; c += 256) {
    float e = __expf(x[c] - m);
    x[c] = e;
    s += e;
  }
  for (int o = 16; o; o >>= 1) s += __shfl_xor_sync(~0u, s, o);
  __syncthreads();
  if (lane == 0) sh[w] = s;
  __syncthreads();
  if (w == 0) {
    s = (lane < 8) ? sh[lane] : 0.f;
    for (int o = 16; o; o >>= 1) s += __shfl_xor_sync(~0u, s, o);
    if (lane == 0) bc = 1.f / s;
  }
  __syncthreads();
  float inv = bc;
  for (int c = tid; c < cT; c += 256) {
    float p = x[c] * inv;
    bf16 hh = __float2bfloat16(p);
    ph[c] = hh;
    pl[c] = __float2bfloat16(p - __bfloat162float(hh));
  }
}

// ---------------------------------------------------------------------------
// AV on MMA: O[b*cL+l, h*96+d] = P(hi/lo) @ V(hi/lo); grid 512, 256 thr.
// cp.async double-buffered chunks of 64 t-positions; V loaded via ldsm.trans.
// ---------------------------------------------------------------------------
#define AV_PSTR 72
#define AV_VSTR 104
#define AV_PARR (64 * AV_PSTR * 2) /* 9216 */
#define AV_VARR (64 * AV_VSTR * 2) /* 13312 */
#define AV_STAGE (2 * AV_PARR + 2 * AV_VARR) /* 45056 */
#define AV_SMEM (2 * AV_STAGE)               /* 90112 */
__global__ __launch_bounds__(256) void attn_av_mma(
    const bf16* __restrict__ Ph, const bf16* __restrict__ Pl,
    const bf16* __restrict__ Vh, const bf16* __restrict__ Vl,
    bf16* __restrict__ Ohi, bf16* __restrict__ Olo) {
  extern __shared__ char sm[];
  const uint32_t sb = smem_u32(sm);
  const int tid = threadIdx.x, lane = tid & 31, wid = tid >> 5;
  const int bh = blockIdx.x, b = bh >> 4, h = bh & 15;
  const int wm = wid >> 1, wn = wid & 1;  // 4 x 2: 16 rows x 48 cols

  auto load_chunk = [&](int ct, int buf) {
    int t0 = ct * 64;
    uint32_t base = sb + buf * AV_STAGE;
#pragma unroll
    for (int it = 0; it < 2; it++) {  // P: 512 16B units per array
      int e = tid + it * 256;
      int r = e >> 3, u = e & 7;
      uint32_t so = r * (AV_PSTR * 2) + u * 16;
      size_t po = (size_t)(bh * cL + r) * cT + t0 + u * 8;
      cp_async16(base + so, Ph + po);
      cp_async16(base + AV_PARR + so, Pl + po);
    }
#pragma unroll
    for (int it = 0; it < 3; it++) {  // V: 768 units per array
      int e = tid + it * 256;
      int r = e / 12, u = e % 12;
      uint32_t so = r * (AV_VSTR * 2) + u * 16;
      size_t vo = (size_t)(b * cT + t0 + r) * cHHD + h * cHD + u * 8;
      cp_async16(base + 2 * AV_PARR + so, Vh + vo);
      cp_async16(base + 2 * AV_PARR + AV_VARR + so, Vl + vo);
    }
    CP_COMMIT();
  };

  float acc[6][4];
#pragma unroll
  for (int nt = 0; nt < 6; nt++)
#pragma unroll
    for (int j = 0; j < 4; j++) acc[nt][j] = 0.f;

  load_chunk(0, 0);
  for (int ct = 0; ct < 37; ct++) {
    int buf = ct & 1;
    if (ct + 1 < 37) {
      load_chunk(ct + 1, buf ^ 1);
      CP_WAIT(1);
    } else {
      CP_WAIT(0);
    }
    __syncthreads();
    uint32_t base = sb + buf * AV_STAGE;
#pragma unroll
    for (int ks = 0; ks < 4; ks++) {
      uint32_t kb = ks * 16;  // t offset within chunk
      uint32_t ap[4], al[4];
      uint32_t aa = base + (wm * 16 + (lane & 15)) * (AV_PSTR * 2) + kb * 2 +
                    (lane >> 4) * 16;
      ldsm_x4(ap, aa);
      ldsm_x4(al, aa + AV_PARR);
#pragma unroll
      for (int nt = 0; nt < 6; nt++) {
        uint32_t ba = base + 2 * AV_PARR +
                      (kb + ((lane >> 3) & 1) * 8 + (lane & 7)) * (AV_VSTR * 2) +
                      (wn * 48 + nt * 8) * 2;
        uint32_t bv[2], blv[2];
        ldsm_x2_trans(bv, ba);
        ldsm_x2_trans(blv, ba + AV_VARR);
        mma16816(acc[nt], ap, bv);
        mma16816(acc[nt], ap, blv);
        mma16816(acc[nt], al, bv);
      }
    }
    __syncthreads();
  }

#pragma unroll
  for (int half = 0; half < 2; half++) {
    int row = b * cL + wm * 16 + (lane >> 2) + half * 8;
#pragma unroll
    for (int nt = 0; nt < 6; nt++) {
      int col = h * cHD + wn * 48 + nt * 8 + (lane & 3) * 2;
      float v0 = acc[nt][half * 2], v1 = acc[nt][half * 2 + 1];
      bf16 h0 = __float2bfloat16(v0), h1 = __float2bfloat16(v1);
      *(__nv_bfloat162*)(Ohi + (size_t)row * cHHD + col) = __nv_bfloat162(h0, h1);
      *(__nv_bfloat162*)(Olo + (size_t)row * cHHD + col) = __nv_bfloat162(
          __float2bfloat16(v0 - __bfloat162float(h0)),
          __float2bfloat16(v1 - __bfloat162float(h1)));
    }
  }
}

// ---------------------------------------------------------------------------
// LN (no affine) + bf16 hi/lo split, rows of length cD
// ---------------------------------------------------------------------------
__global__ void ln_split_kernel(const float* __restrict__ x,
                                bf16* __restrict__ hi, bf16* __restrict__ lo) {
  int row = blockIdx.x;
  const float* xr = x + (size_t)row * cD;
  float s = 0.f, s2 = 0.f;
  for (int c = threadIdx.x; c < cD; c += 256) {
    float v = xr[c];
    s += v; s2 += v * v;
  }
  __shared__ float sh[64];
  for (int o = 16; o; o >>= 1) {
    s += __shfl_xor_sync(~0u, s, o);
    s2 += __shfl_xor_sync(~0u, s2, o);
  }
  int w = threadIdx.x >> 5, lane = threadIdx.x & 31;
  if (lane == 0) { sh[w] = s; sh[w + 32] = s2; }
  __syncthreads();
  if (w == 0) {
    s = (lane < 8) ? sh[lane] : 0.f;
    s2 = (lane < 8) ? sh[lane + 32] : 0.f;
    for (int o = 16; o; o >>= 1) {
      s += __shfl_xor_sync(~0u, s, o);
      s2 += __shfl_xor_sync(~0u, s2, o);
    }
    if (lane == 0) { sh[0] = s; sh[1] = s2; }
  }
  __syncthreads();
  float mean = sh[0] * (1.f / cD);
  float rstd = rsqrtf(sh[1] * (1.f / cD) - mean * mean + cEPS);
  for (int c = threadIdx.x; c < cD; c += 256) {
    float v = (xr[c] - mean) * rstd;
    bf16 h = __float2bfloat16(v);
    hi[(size_t)row * cD + c] = h;
    lo[(size_t)row * cD + c] = __float2bfloat16(v - __bfloat162float(h));
  }
}

// ---------------------------------------------------------------------------
// Weight prep (transposed hi/lo + rank-1 bias)
// ---------------------------------------------------------------------------
__global__ void wprep_kernel(const float* __restrict__ W,
                             const float* __restrict__ g,
                             const float* __restrict__ b,
                             bf16* __restrict__ Whi, bf16* __restrict__ Wlo,
                             float* __restrict__ bias, int Kdim, int Nw) {
  int n = blockIdx.x;
  float bs = 0.f;
  for (int k = threadIdx.x; k < Kdim; k += 256) {
    float w = W[(size_t)k * Nw + n];
    float v = (g != nullptr) ? g[k] * w : w;
    bf16 h = __float2bfloat16(v);
    Whi[(size_t)n * Kdim + k] = h;
    Wlo[(size_t)n * Kdim + k] = __float2bfloat16(v - __bfloat162float(h));
    if (b != nullptr) bs += b[k] * w;
  }
  if (bias != nullptr) {
    __shared__ float sh[8];
    for (int o = 16; o; o >>= 1) bs += __shfl_xor_sync(~0u, bs, o);
    int w8 = threadIdx.x >> 5, lane = threadIdx.x & 31;
    if (lane == 0) sh[w8] = bs;
    __syncthreads();
    if (threadIdx.x == 0) {
      float t = 0.f;
      for (int i = 0; i < 8; i++) t += sh[i];
      bias[n] = t;
    }
  }
}

// ---------------------------------------------------------------------------
// Broadcast latents -> (B, L, D)
// ---------------------------------------------------------------------------
__global__ void bcast_latents_kernel(const float* __restrict__ lat,
                                     float* __restrict__ out) {
  int idx = blockIdx.x * 256 + threadIdx.x;
  out[idx] = lat[idx % (cL * cD)];
}

// ---------------------------------------------------------------------------
// Final LayerNorm with affine (block per row)
// ---------------------------------------------------------------------------
__global__ void ln_rows_kernel(const float* __restrict__ x,
                               float* __restrict__ y,
                               const float* __restrict__ g,
                               const float* __restrict__ b) {
  int row = blockIdx.x;
  const float* xr = x + (size_t)row * cD;
  float* yr = y + (size_t)row * cD;
  float s = 0.f, s2 = 0.f;
  for (int c = threadIdx.x; c < cD; c += 256) {
    float v = xr[c];
    s += v; s2 += v * v;
  }
  __shared__ float sh[64];
  for (int o = 16; o; o >>= 1) {
    s += __shfl_xor_sync(~0u, s, o);
    s2 += __shfl_xor_sync(~0u, s2, o);
  }
  int w = threadIdx.x >> 5, lane = threadIdx.x & 31;
  if (lane == 0) { sh[w] = s; sh[w + 32] = s2; }
  __syncthreads();
  if (w == 0) {
    s = (lane < 8) ? sh[lane] : 0.f;
    s2 = (lane < 8) ? sh[lane + 32] : 0.f;
    for (int o = 16; o; o >>= 1) {
      s += __shfl_xor_sync(~0u, s, o);
      s2 += __shfl_xor_sync(~0u, s2, o);
    }
    if (lane == 0) { sh[0] = s; sh[1] = s2; }
  }
  __syncthreads();
  float mean = sh[0] * (1.f / cD);
  float rstd = rsqrtf(sh[1] * (1.f / cD) - mean * mean + cEPS);
  for (int c = threadIdx.x; c < cD; c += 256)
    yr[c] = (xr[c] - mean) * rstd * g[c] + b[c];
}

// ---------------------------------------------------------------------------
// Per-head LN over 96-elem subrows (warp per row) -> bf16 hi/lo outputs
// ---------------------------------------------------------------------------
__global__ void ln_head_split_kernel(const float* __restrict__ x,
                                     const float* __restrict__ g,
                                     const float* __restrict__ b,
                                     bf16* __restrict__ hi,
                                     bf16* __restrict__ lo, int nrows) {
  int r = blockIdx.x * 4 + (threadIdx.x >> 5);
  if (r >= nrows) return;
  int lane = threadIdx.x & 31;
  const float* xr = x + (size_t)r * cHD;
  float v0 = xr[lane], v1 = xr[lane + 32], v2 = xr[lane + 64];
  float s = v0 + v1 + v2;
  float s2 = v0 * v0 + v1 * v1 + v2 * v2;
  for (int o = 16; o; o >>= 1) {
    s += __shfl_xor_sync(~0u, s, o);
    s2 += __shfl_xor_sync(~0u, s2, o);
  }
  float mean = s * (1.f / 96.f);
  float rstd = rsqrtf(s2 * (1.f / 96.f) - mean * mean + cEPS);
  float y0 = (v0 - mean) * rstd * g[lane] + b[lane];
  float y1 = (v1 - mean) * rstd * g[lane + 32] + b[lane + 32];
  float y2 = (v2 - mean) * rstd * g[lane + 64] + b[lane + 64];
  bf16* hr = hi + (size_t)r * cHD;
  bf16* lr = lo + (size_t)r * cHD;
  bf16 h0 = __float2bfloat16(y0), h1 = __float2bfloat16(y1),
       h2 = __float2bfloat16(y2);
  hr[lane] = h0; hr[lane + 32] = h1; hr[lane + 64] = h2;
  lr[lane] = __float2bfloat16(y0 - __bfloat162float(h0));
  lr[lane + 32] = __float2bfloat16(y1 - __bfloat162float(h1));
  lr[lane + 64] = __float2bfloat16(y2 - __bfloat162float(h2));
}

// ---------------------------------------------------------------------------
// Host orchestration
// ---------------------------------------------------------------------------
extern "C" void kernel_launch(void* const* d_in, const int* in_sizes, int n_in,
                              void* d_out, int out_size) {
  (void)in_sizes; (void)n_in; (void)out_size;
  const float* context = (const float*)d_in[0];
  const float* latents = (const float*)d_in[1];
  const float* ctx_g = (const float*)d_in[2];
  const float* ctx_b = (const float*)d_in[3];
  const float* lat_g = (const float*)d_in[4];
  const float* lat_b = (const float*)d_in[5];
  const float* q_g = (const float*)d_in[6];
  const float* q_b = (const float*)d_in[7];
  const float* k_g = (const float*)d_in[8];
  const float* k_b = (const float*)d_in[9];
  const float* Wq = (const float*)d_in[10];
  const float* Wk = (const float*)d_in[11];
  const float* Wv = (const float*)d_in[12];
  const float* Wo = (const float*)d_in[13];
  const float* mlp_g = (const float*)d_in[14];
  const float* mlp_b = (const float*)d_in[15];
  const float* Wfc = (const float*)d_in[16];
  const float* Wcp = (const float*)d_in[17];
  const float* f_g = (const float*)d_in[18];
  const float* f_b = (const float*)d_in[19];
  float* out = (float*)d_out;

#define SYM(var, sym) cudaGetSymbolAddress((void**)&var, sym)
  bf16 *ctxhi, *ctxlo, *lnhi, *lnlo, *atthi, *attlo, *mlphi, *mlplo;
  bf16 *qhi, *qlo, *khi, *klo, *vhi, *vlo, *phi, *plo;
  bf16 *wqh, *wql, *wkch, *wkcl, *wklh, *wkll, *wvch, *wvcl, *wvlh, *wvll,
      *woh, *wol, *wfch, *wfcl, *wcph, *wcpl;
  float *bQ, *bKc, *bKl, *bVc, *bVl, *bFc;
  float *lat, *Qp, *Kp, *Scp;
  SYM(ctxhi, g_ctx_hi); SYM(ctxlo, g_ctx_lo);
  SYM(lnhi, g_latln_hi); SYM(lnlo, g_latln_lo);
  SYM(atthi, g_att_hi); SYM(attlo, g_att_lo);
  SYM(mlphi, g_mlp_hi); SYM(mlplo, g_mlp_lo);
  SYM(qhi, g_Q_hi); SYM(qlo, g_Q_lo);
  SYM(khi, g_K_hi); SYM(klo, g_K_lo);
  SYM(vhi, g_V_hi); SYM(vlo, g_V_lo);
  SYM(phi, g_P_hi); SYM(plo, g_P_lo);
  SYM(wqh, g_wq_hi); SYM(wql, g_wq_lo);
  SYM(wkch, g_wkc_hi); SYM(wkcl, g_wkc_lo);
  SYM(wklh, g_wkl_hi); SYM(wkll, g_wkl_lo);
  SYM(wvch, g_wvc_hi); SYM(wvcl, g_wvc_lo);
  SYM(wvlh, g_wvl_hi); SYM(wvll, g_wvl_lo);
  SYM(woh, g_wo_hi); SYM(wol, g_wo_lo);
  SYM(wfch, g_wfc_hi); SYM(wfcl, g_wfc_lo);
  SYM(wcph, g_wcp_hi); SYM(wcpl, g_wcp_lo);
  SYM(bQ, g_biasQ); SYM(bKc, g_biasKc); SYM(bKl, g_biasKl);
  SYM(bVc, g_biasVc); SYM(bVl, g_biasVl); SYM(bFc, g_biasFc);
  SYM(lat, g_lat); SYM(Qp, g_Q); SYM(Kp, g_K); SYM(Scp, g_scores);
#undef SYM

  cudaFuncSetAttribute(mma_gemm_split,
                       cudaFuncAttributeMaxDynamicSharedMemorySize, MG_SMEM);
  cudaFuncSetAttribute(attn_scores_mma,
                       cudaFuncAttributeMaxDynamicSharedMemorySize, SCM_SMEM);
  cudaFuncSetAttribute(attn_av_mma,
                       cudaFuncAttributeMaxDynamicSharedMemorySize, AV_SMEM);

  // once: LN(context) -> bf16 hi/lo ; latent broadcast
  ln_split_kernel<<<cMCTX, 256>>>(context, ctxhi, ctxlo);
  bcast_latents_kernel<<<(cML * cD) / 256, 256>>>(latents, lat);

  auto mma = [&](const bf16* Ah, const bf16* Al, const bf16* Bh,
                 const bf16* Bl, const float* bias, const float* R, float* C,
                 bf16* Ch, bf16* Cl, int M, int N, int Kd, int relu, int rpbIn,
                 int rpbOut, int rowOff) {
    dim3 grid(N / 128, M / 128);
    mma_gemm_split<<<grid, 256, MG_SMEM>>>(Ah, Al, Bh, Bl, bias, R, C, Ch, Cl,
                                           Kd, N, relu, rpbIn, rpbOut, rowOff);
  };

  for (int i = 0; i < cDEPTH; i++) {
    const float* Wq_i = Wq + (size_t)i * cD * cHHD;
    const float* Wk_i = Wk + (size_t)i * cD * cHHD;
    const float* Wv_i = Wv + (size_t)i * cD * cHHD;
    const float* Wo_i = Wo + (size_t)i * cHHD * cD;
    const float* Wfc_i = Wfc + (size_t)i * cD * cI;
    const float* Wcp_i = Wcp + (size_t)i * cI * cD;
    const float* lg = lat_g + i * cD;
    const float* lb = lat_b + i * cD;

    // LN(latents) -> normalized hi/lo (affine folded into weights)
    ln_split_kernel<<<cML, 256>>>(lat, lnhi, lnlo);

    // weight preps
    wprep_kernel<<<cHHD, 256>>>(Wq_i, lg, lb, wqh, wql, bQ, cD, cHHD);
    wprep_kernel<<<cHHD, 256>>>(Wk_i, ctx_g + i * cD, ctx_b + i * cD, wkch,
                                wkcl, bKc, cD, cHHD);
    wprep_kernel<<<cHHD, 256>>>(Wk_i, lg, lb, wklh, wkll, bKl, cD, cHHD);
    wprep_kernel<<<cHHD, 256>>>(Wv_i, ctx_g + i * cD, ctx_b + i * cD, wvch,
                                wvcl, bVc, cD, cHHD);
    wprep_kernel<<<cHHD, 256>>>(Wv_i, lg, lb, wvlh, wvll, bVl, cD, cHHD);

    // Q (fp32 out for per-head LN)
    mma(lnhi, lnlo, wqh, wql, bQ, nullptr, Qp, nullptr, nullptr, cML, cHHD, cD,
        0, cML, cML, 0);
    // K (fp32 for per-head LN), context + latent rows
    mma(ctxhi, ctxlo, wkch, wkcl, bKc, nullptr, Kp, nullptr, nullptr, cMCTX,
        cHHD, cD, 0, cS, cT, 0);
    mma(lnhi, lnlo, wklh, wkll, bKl, nullptr, Kp, nullptr, nullptr, cML, cHHD,
        cD, 0, cL, cT, cS);
    // V straight to hi/lo (no LN on V)
    mma(ctxhi, ctxlo, wvch, wvcl, bVc, nullptr, nullptr, vhi, vlo, cMCTX, cHHD,
        cD, 0, cS, cT, 0);
    mma(lnhi, lnlo, wvlh, wvll, bVl, nullptr, nullptr, vhi, vlo, cML, cHHD, cD,
        0, cL, cT, cS);

    // per-head q/k LN -> hi/lo
    ln_head_split_kernel<<<(cML * cH) / 4, 128>>>(Qp, q_g + i * cHD,
                                                  q_b + i * cHD, qhi, qlo,
                                                  cML * cH);
    ln_head_split_kernel<<<(cB * cT * cH) / 4, 128>>>(Kp, k_g + i * cHD,
                                                      k_b + i * cHD, khi, klo,
                                                      cB * cT * cH);

    // attention on MMA
    attn_scores_mma<<<dim3(cT / 64, cB * cH), 256, SCM_SMEM>>>(qhi, qlo, khi,
                                                               klo, Scp);
    softmax_split_kernel<<<cB * cH * cL, 256>>>(Scp, phi, plo);
    attn_av_mma<<<cB * cH, 256, AV_SMEM>>>(phi, plo, vhi, vlo, atthi, attlo);

    // lat = att @ Wo + lat
    wprep_kernel<<<cD, 256>>>(Wo_i, nullptr, nullptr, woh, wol, nullptr, cHHD,
                              cD);
    mma(atthi, attlo, woh, wol, nullptr, lat, lat, nullptr, nullptr, cML, cD,
        cHHD, 0, cML, cML, 0);

    // MLP
    ln_split_kernel<<<cML, 256>>>(lat, lnhi, lnlo);
    wprep_kernel<<<cI, 256>>>(Wfc_i, mlp_g + i * cD, mlp_b + i * cD, wfch, wfcl,
                              bFc, cD, cI);
    mma(lnhi, lnlo, wfch, wfcl, bFc, nullptr, nullptr, mlphi, mlplo, cML, cI,
        cD, 1, cML, cML, 0);
    wprep_kernel<<<cD, 256>>>(Wcp_i, nullptr, nullptr, wcph, wcpl, nullptr, cI,
                              cD);
    mma(mlphi, mlplo, wcph, wcpl, nullptr, lat, lat, nullptr, nullptr, cML, cD,
        cI, 0, cML, cML, 0);
  }

  ln_rows_kernel<<<cML, 256>>>(lat, out, f_g, f_b);
}

// round 6
// speedup vs baseline: 2.4310x; 1.1165x over previous
#include <cuda_runtime.h>
#include <cuda_bf16.h>
#include <cstdint>
#include <cstddef>

// ---------------------------------------------------------------------------
// Problem constants
// ---------------------------------------------------------------------------
#define cB 32
#define cS 2304
#define cD 1280
#define cDEPTH 6
#define cH 16
#define cHD 96
#define cL 64
#define cI 5120
#define cT (cS + cL)      /* 2368 */
#define cHHD (cH * cHD)   /* 1536 */
#define cEPS 1e-5f
#define cMCTX (cB * cS)   /* 73728 ctx rows */
#define cML (cB * cL)     /* 2048 latent rows */

typedef __nv_bfloat16 bf16;

// ---------------------------------------------------------------------------
// Scratch (device globals: allocation-free rule)
// ---------------------------------------------------------------------------
__device__ bf16 g_ctx_hi[(size_t)cMCTX * cD];
__device__ bf16 g_ctx_lo[(size_t)cMCTX * cD];
__device__ bf16 g_latln_hi[cML * cD];
__device__ bf16 g_latln_lo[cML * cD];
__device__ bf16 g_att_hi[cML * cHHD];
__device__ bf16 g_att_lo[cML * cHHD];
__device__ bf16 g_mlp_hi[(size_t)cML * cI];
__device__ bf16 g_mlp_lo[(size_t)cML * cI];
__device__ bf16 g_Q_hi[cML * cHHD], g_Q_lo[cML * cHHD];
__device__ bf16 g_K_hi[(size_t)cB * cT * cHHD], g_K_lo[(size_t)cB * cT * cHHD];
__device__ bf16 g_V_hi[(size_t)cB * cT * cHHD], g_V_lo[(size_t)cB * cT * cHHD];
__device__ bf16 g_P_hi[(size_t)cB * cH * cL * cT];
__device__ bf16 g_P_lo[(size_t)cB * cH * cL * cT];
__device__ bf16 g_wq_hi[cHHD * cD],  g_wq_lo[cHHD * cD];
__device__ bf16 g_wkc_hi[cHHD * cD], g_wkc_lo[cHHD * cD];
__device__ bf16 g_wkl_hi[cHHD * cD], g_wkl_lo[cHHD * cD];
__device__ bf16 g_wvc_hi[cHHD * cD], g_wvc_lo[cHHD * cD];
__device__ bf16 g_wvl_hi[cHHD * cD], g_wvl_lo[cHHD * cD];
__device__ bf16 g_wo_hi[cD * cHHD],  g_wo_lo[cD * cHHD];
__device__ bf16 g_wfc_hi[(size_t)cI * cD], g_wfc_lo[(size_t)cI * cD];
__device__ bf16 g_wcp_hi[(size_t)cD * cI], g_wcp_lo[(size_t)cD * cI];
__device__ float g_biasQ[cHHD], g_biasKc[cHHD], g_biasKl[cHHD];
__device__ float g_biasVc[cHHD], g_biasVl[cHHD], g_biasFc[cI];
__device__ float g_lat[cML * cD];
__device__ float g_Q[cML * cHHD];
__device__ float g_K[(size_t)cB * cT * cHHD];
__device__ float g_scores[(size_t)cB * cH * cL * cT];

// ---------------------------------------------------------------------------
// MMA helpers (base-PTX: ldmatrix + mma.sync, sm_80+)
// ---------------------------------------------------------------------------
__device__ __forceinline__ uint32_t smem_u32(const void* p) {
  uint32_t a;
  asm("{ .reg .u64 t; cvta.to.shared.u64 t, %1; cvt.u32.u64 %0, t; }"
      : "=r"(a) : "l"(p));
  return a;
}
__device__ __forceinline__ void cp_async16(uint32_t saddr, const void* gptr) {
  asm volatile("cp.async.cg.shared.global [%0], [%1], 16;" ::"r"(saddr),
               "l"(gptr)
               : "memory");
}
#define CP_COMMIT() asm volatile("cp.async.commit_group;" ::: "memory")
#define CP_WAIT(N) asm volatile("cp.async.wait_group %0;" ::"n"(N) : "memory")

__device__ __forceinline__ void ldsm_x4(uint32_t* d, uint32_t addr) {
  asm volatile("ldmatrix.sync.aligned.m8n8.x4.shared.b16 {%0,%1,%2,%3},[%4];"
               : "=r"(d[0]), "=r"(d[1]), "=r"(d[2]), "=r"(d[3])
               : "r"(addr));
}
__device__ __forceinline__ void ldsm_x2(uint32_t* d, uint32_t addr) {
  asm volatile("ldmatrix.sync.aligned.m8n8.x2.shared.b16 {%0,%1},[%2];"
               : "=r"(d[0]), "=r"(d[1])
               : "r"(addr));
}
__device__ __forceinline__ void ldsm_x2_trans(uint32_t* d, uint32_t addr) {
  asm volatile("ldmatrix.sync.aligned.m8n8.x2.trans.shared.b16 {%0,%1},[%2];"
               : "=r"(d[0]), "=r"(d[1])
               : "r"(addr));
}
__device__ __forceinline__ void mma16816(float* c, const uint32_t* a,
                                         const uint32_t* b) {
  asm volatile(
      "mma.sync.aligned.m16n8k16.row.col.f32.bf16.bf16.f32 "
      "{%0,%1,%2,%3},{%4,%5,%6,%7},{%8,%9},{%0,%1,%2,%3};"
      : "+f"(c[0]), "+f"(c[1]), "+f"(c[2]), "+f"(c[3])
      : "r"(a[0]), "r"(a[1]), "r"(a[2]), "r"(a[3]), "r"(b[0]), "r"(b[1]));
}

// ---------------------------------------------------------------------------
// Fused K+V bf16-split GEMM (shares A operand; 512 thr; 3-stage, 1 sync/chunk)
//   warps 0-7 -> K tile (fp32 out + biasK, row remap)
//   warps 8-15 -> V tile (bf16 hi/lo out + biasV, row remap)
//   A [M][1280] hi/lo; Bk/Bv [1536][1280] hi/lo (transposed, K-contiguous)
// ---------------------------------------------------------------------------
#define FK_BK 32
#define FK_NC (cD / FK_BK) /* 40 */
#define FK_STRIDE 40
#define FK_ARR (128 * FK_STRIDE * 2) /* 10240 */
#define FK_STAGE (6 * FK_ARR)        /* 61440 */
#define FK_SMEM (3 * FK_STAGE)       /* 184320 */

__global__ __launch_bounds__(512) void fused_kv_gemm(
    const bf16* __restrict__ Ahi, const bf16* __restrict__ Alo,
    const bf16* __restrict__ Bkh, const bf16* __restrict__ Bkl,
    const bf16* __restrict__ Bvh, const bf16* __restrict__ Bvl,
    const float* __restrict__ biasK, const float* __restrict__ biasV,
    float* __restrict__ Kout, bf16* __restrict__ Vhi, bf16* __restrict__ Vlo,
    int rpbIn, int rpbOut, int rowOff) {
  extern __shared__ char sm[];
  const uint32_t sb = smem_u32(sm);
  const int tid = threadIdx.x, lane = tid & 31, wid = tid >> 5;
  const int grp = wid >> 3;  // 0=K, 1=V
  const int gw = wid & 7;
  const int wm = gw & 1, wn = gw >> 1;
  const int m0 = blockIdx.y * 128, n0 = blockIdx.x * 128;

  const bf16* gA0 = Ahi + (size_t)m0 * cD;
  const bf16* gA1 = Alo + (size_t)m0 * cD;
  const bf16* gK0 = Bkh + (size_t)n0 * cD;
  const bf16* gK1 = Bkl + (size_t)n0 * cD;
  const bf16* gV0 = Bvh + (size_t)n0 * cD;
  const bf16* gV1 = Bvl + (size_t)n0 * cD;

  float acc[4][4][4];
#pragma unroll
  for (int mt = 0; mt < 4; mt++)
#pragma unroll
    for (int nt = 0; nt < 4; nt++)
#pragma unroll
      for (int j = 0; j < 4; j++) acc[mt][nt][j] = 0.f;

  const int lr = tid >> 2;  // 0..127
  const int lu = tid & 3;   // 16B unit within 32-elem row
  auto load_chunk = [&](int c, int buf) {
    int kk = c * FK_BK;
    uint32_t base = sb + buf * FK_STAGE;
    uint32_t so = lr * (FK_STRIDE * 2) + lu * 16;
    size_t go = (size_t)lr * cD + kk + lu * 8;
    cp_async16(base + 0 * FK_ARR + so, gA0 + go);
    cp_async16(base + 1 * FK_ARR + so, gA1 + go);
    cp_async16(base + 2 * FK_ARR + so, gK0 + go);
    cp_async16(base + 3 * FK_ARR + so, gK1 + go);
    cp_async16(base + 4 * FK_ARR + so, gV0 + go);
    cp_async16(base + 5 * FK_ARR + so, gV1 + go);
    CP_COMMIT();
  };

  load_chunk(0, 0);
  load_chunk(1, 1);

  const uint32_t aRow = (wm * 64 + (lane & 15)) * (FK_STRIDE * 2);
  const uint32_t aColB = ((lane >> 4) << 3) * 2;
  const uint32_t bRow = (wn * 32 + (lane & 7)) * (FK_STRIDE * 2);
  const uint32_t bColB = (((lane >> 3) & 1) << 3) * 2;
  const uint32_t bOff = (grp ? 4u : 2u) * FK_ARR;

  for (int c = 0; c < FK_NC; c++) {
    if (c + 1 < FK_NC) { CP_WAIT(1); } else { CP_WAIT(0); }
    __syncthreads();
    if (c + 2 < FK_NC) load_chunk(c + 2, (c + 2) % 3);
    uint32_t base = sb + (c % 3) * FK_STAGE;
#pragma unroll
    for (int ks = 0; ks < 2; ks++) {
      uint32_t kb = ks * 32;
      uint32_t ah[4][4], al[4][4];
#pragma unroll
      for (int mt = 0; mt < 4; mt++) {
        uint32_t ad = base + aRow + mt * 16 * (FK_STRIDE * 2) + kb + aColB;
        ldsm_x4(ah[mt], ad);
        ldsm_x4(al[mt], ad + FK_ARR);
      }
#pragma unroll
      for (int nt = 0; nt < 4; nt++) {
        uint32_t bd = base + bOff + bRow + nt * 8 * (FK_STRIDE * 2) + kb + bColB;
        uint32_t bh2[2], bl2[2];
        ldsm_x2(bh2, bd);
        ldsm_x2(bl2, bd + FK_ARR);
#pragma unroll
        for (int mt = 0; mt < 4; mt++) {
          mma16816(acc[mt][nt], ah[mt], bh2);
          mma16816(acc[mt][nt], ah[mt], bl2);
          mma16816(acc[mt][nt], al[mt], bh2);
        }
      }
    }
  }

  // epilogue with row remap
#pragma unroll
  for (int mt = 0; mt < 4; mt++) {
    int mloc = wm * 64 + mt * 16 + (lane >> 2);
#pragma unroll
    for (int half = 0; half < 2; half++) {
      int m = m0 + mloc + half * 8;
      int orow = (m / rpbIn) * rpbOut + rowOff + (m % rpbIn);
#pragma unroll
      for (int nt = 0; nt < 4; nt++) {
        int n = n0 + wn * 32 + nt * 8 + (lane & 3) * 2;
        float v0 = acc[mt][nt][half * 2 + 0];
        float v1 = acc[mt][nt][half * 2 + 1];
        if (grp == 0) {
          v0 += biasK[n]; v1 += biasK[n + 1];
          *(float2*)(Kout + (size_t)orow * cHHD + n) = make_float2(v0, v1);
        } else {
          v0 += biasV[n]; v1 += biasV[n + 1];
          bf16 h0 = __float2bfloat16(v0), h1 = __float2bfloat16(v1);
          *(__nv_bfloat162*)(Vhi + (size_t)orow * cHHD + n) =
              __nv_bfloat162(h0, h1);
          *(__nv_bfloat162*)(Vlo + (size_t)orow * cHHD + n) = __nv_bfloat162(
              __float2bfloat16(v0 - __bfloat162float(h0)),
              __float2bfloat16(v1 - __bfloat162float(h1)));
        }
      }
    }
  }
}

// ---------------------------------------------------------------------------
// Generalized pipelined bf16-split MMA GEMM (Q, Wo, Wfc, Wcp) — unchanged.
// ---------------------------------------------------------------------------
#define MG_BK 32
#define MG_STRIDE 40
#define MG_ARR (128 * MG_STRIDE * 2)
#define MG_BUF (4 * MG_ARR)
#define MG_SMEM (2 * MG_BUF)

__global__ __launch_bounds__(256) void mma_gemm_split(
    const bf16* __restrict__ Ahi, const bf16* __restrict__ Alo,
    const bf16* __restrict__ Bhi, const bf16* __restrict__ Blo,
    const float* __restrict__ bias, const float* __restrict__ R,
    float* __restrict__ C, bf16* __restrict__ Chi, bf16* __restrict__ Clo,
    int Kdim, int cN, int relu, int rpbIn, int rpbOut, int rowOff) {
  extern __shared__ char sm[];
  const uint32_t sb = smem_u32(sm);
  const int tid = threadIdx.x;
  const int lane = tid & 31, wid = tid >> 5;
  const int wm = wid & 1, wn = wid >> 1;
  const int m0 = blockIdx.y * 128, n0 = blockIdx.x * 128;
  const int nc = Kdim / MG_BK;

  const bf16* gA0 = Ahi + (size_t)m0 * Kdim;
  const bf16* gA1 = Alo + (size_t)m0 * Kdim;
  const bf16* gB0 = Bhi + (size_t)n0 * Kdim;
  const bf16* gB1 = Blo + (size_t)n0 * Kdim;

  float acc[4][4][4];
#pragma unroll
  for (int mt = 0; mt < 4; mt++)
#pragma unroll
    for (int nt = 0; nt < 4; nt++)
#pragma unroll
      for (int j = 0; j < 4; j++) acc[mt][nt][j] = 0.f;

  const int lr = tid >> 2;
  const int lu = tid & 3;
  auto load_chunk = [&](int c, int buf) {
    int kk = c * MG_BK;
    uint32_t base = sb + buf * MG_BUF;
#pragma unroll
    for (int j = 0; j < 2; j++) {
      int r = lr + j * 64;
      uint32_t so = r * (MG_STRIDE * 2) + lu * 16;
      size_t go = (size_t)r * Kdim + kk + lu * 8;
      cp_async16(base + 0 * MG_ARR + so, gA0 + go);
      cp_async16(base + 1 * MG_ARR + so, gA1 + go);
      cp_async16(base + 2 * MG_ARR + so, gB0 + go);
      cp_async16(base + 3 * MG_ARR + so, gB1 + go);
    }
    CP_COMMIT();
  };

  load_chunk(0, 0);

  const uint32_t aRow = (wm * 64 + (lane & 15)) * (MG_STRIDE * 2);
  const uint32_t aColB = ((lane >> 4) << 3) * 2;
  const uint32_t bRow = (wn * 32 + (lane & 7)) * (MG_STRIDE * 2);
  const uint32_t bColB = (((lane >> 3) & 1) << 3) * 2;

  for (int c = 0; c < nc; c++) {
    int buf = c & 1;
    if (c + 1 < nc) {
      load_chunk(c + 1, buf ^ 1);
      CP_WAIT(1);
    } else {
      CP_WAIT(0);
    }
    __syncthreads();
    uint32_t base = sb + buf * MG_BUF;
#pragma unroll
    for (int ks = 0; ks < 2; ks++) {
      uint32_t kb = ks * 32;
      uint32_t ah[4][4], al[4][4], bh[4][2], bl[4][2];
#pragma unroll
      for (int mt = 0; mt < 4; mt++) {
        uint32_t ad = base + aRow + mt * 16 * (MG_STRIDE * 2) + kb + aColB;
        ldsm_x4(ah[mt], ad);
        ldsm_x4(al[mt], ad + MG_ARR);
      }
#pragma unroll
      for (int nt = 0; nt < 4; nt++) {
        uint32_t bd =
            base + 2 * MG_ARR + bRow + nt * 8 * (MG_STRIDE * 2) + kb + bColB;
        ldsm_x2(bh[nt], bd);
        ldsm_x2(bl[nt], bd + MG_ARR);
      }
#pragma unroll
      for (int mt = 0; mt < 4; mt++)
#pragma unroll
        for (int nt = 0; nt < 4; nt++) {
          mma16816(acc[mt][nt], ah[mt], bh[nt]);
          mma16816(acc[mt][nt], ah[mt], bl[nt]);
          mma16816(acc[mt][nt], al[mt], bh[nt]);
        }
    }
    __syncthreads();
  }

#pragma unroll
  for (int mt = 0; mt < 4; mt++) {
    int mloc = wm * 64 + mt * 16 + (lane >> 2);
#pragma unroll
    for (int half = 0; half < 2; half++) {
      int m = m0 + mloc + half * 8;
      int orow = (m / rpbIn) * rpbOut + rowOff + (m % rpbIn);
#pragma unroll
      for (int nt = 0; nt < 4; nt++) {
        int n = n0 + wn * 32 + nt * 8 + (lane & 3) * 2;
        float v0 = acc[mt][nt][half * 2 + 0];
        float v1 = acc[mt][nt][half * 2 + 1];
        if (bias != nullptr) { v0 += bias[n]; v1 += bias[n + 1]; }
        if (R != nullptr) {
          float2 rv = *(const float2*)(R + (size_t)orow * cN + n);
          v0 += rv.x; v1 += rv.y;
        }
        if (relu) { v0 = fmaxf(v0, 0.f); v1 = fmaxf(v1, 0.f); }
        if (C != nullptr)
          *(float2*)(C + (size_t)orow * cN + n) = make_float2(v0, v1);
        if (Chi != nullptr) {
          bf16 h0 = __float2bfloat16(v0);
          bf16 h1 = __float2bfloat16(v1);
          *(__nv_bfloat162*)(Chi + (size_t)orow * cN + n) =
              __nv_bfloat162(h0, h1);
          *(__nv_bfloat162*)(Clo + (size_t)orow * cN + n) = __nv_bfloat162(
              __float2bfloat16(v0 - __bfloat162float(h0)),
              __float2bfloat16(v1 - __bfloat162float(h1)));
        }
      }
    }
  }
}

// ---------------------------------------------------------------------------
// Attention scores on MMA (unchanged)
// ---------------------------------------------------------------------------
#define SCM_STRIDE 104
#define SCM_ARR (64 * SCM_STRIDE * 2)
#define SCM_SMEM (4 * SCM_ARR)
__global__ __launch_bounds__(256) void attn_scores_mma(
    const bf16* __restrict__ Qh, const bf16* __restrict__ Ql,
    const bf16* __restrict__ Kh, const bf16* __restrict__ Kl,
    float* __restrict__ Sc) {
  extern __shared__ char sm[];
  const uint32_t sb = smem_u32(sm);
  const int tid = threadIdx.x, lane = tid & 31, wid = tid >> 5;
  const int bh = blockIdx.y, b = bh >> 4, h = bh & 15;
  const int t0 = blockIdx.x * 64;

#pragma unroll
  for (int it = 0; it < 3; it++) {
    int e = tid + it * 256;
    int r = e / 12, u = e % 12;
    uint32_t so = r * (SCM_STRIDE * 2) + u * 16;
    size_t qo = (size_t)(b * cL + r) * cHHD + h * cHD + u * 8;
    size_t ko = (size_t)(b * cT + t0 + r) * cHHD + h * cHD + u * 8;
    *(uint4*)(sm + 0 * SCM_ARR + so) = *(const uint4*)(Qh + qo);
    *(uint4*)(sm + 1 * SCM_ARR + so) = *(const uint4*)(Ql + qo);
    *(uint4*)(sm + 2 * SCM_ARR + so) = *(const uint4*)(Kh + ko);
    *(uint4*)(sm + 3 * SCM_ARR + so) = *(const uint4*)(Kl + ko);
  }
  __syncthreads();

  const int wm = wid & 1, wn = wid >> 1;
  float acc[2][2][4];
#pragma unroll
  for (int mt = 0; mt < 2; mt++)
#pragma unroll
    for (int nt = 0; nt < 2; nt++)
#pragma unroll
      for (int j = 0; j < 4; j++) acc[mt][nt][j] = 0.f;

#pragma unroll
  for (int ks = 0; ks < 6; ks++) {
    uint32_t kb = ks * 32;
    uint32_t ah[2][4], al[2][4], bh2[2][2], bl2[2][2];
#pragma unroll
    for (int mt = 0; mt < 2; mt++) {
      uint32_t ad = sb + (wm * 32 + mt * 16 + (lane & 15)) * (SCM_STRIDE * 2) +
                    kb + (lane >> 4) * 16;
      ldsm_x4(ah[mt], ad);
      ldsm_x4(al[mt], ad + SCM_ARR);
    }
#pragma unroll
    for (int nt = 0; nt < 2; nt++) {
      uint32_t bd = sb + 2 * SCM_ARR +
                    (wn * 16 + nt * 8 + (lane & 7)) * (SCM_STRIDE * 2) + kb +
                    ((lane >> 3) & 1) * 16;
      ldsm_x2(bh2[nt], bd);
      ldsm_x2(bl2[nt], bd + SCM_ARR);
    }
#pragma unroll
    for (int mt = 0; mt < 2; mt++)
#pragma unroll
      for (int nt = 0; nt < 2; nt++) {
        mma16816(acc[mt][nt], ah[mt], bh2[nt]);
        mma16816(acc[mt][nt], ah[mt], bl2[nt]);
        mma16816(acc[mt][nt], al[mt], bh2[nt]);
      }
  }

  const float scale = 0.102062072615966f;
#pragma unroll
  for (int mt = 0; mt < 2; mt++)
#pragma unroll
    for (int half = 0; half < 2; half++) {
      int row = wm * 32 + mt * 16 + (lane >> 2) + half * 8;
#pragma unroll
      for (int nt = 0; nt < 2; nt++) {
        int col = t0 + wn * 16 + nt * 8 + (lane & 3) * 2;
        *(float2*)(Sc + ((size_t)bh * cL + row) * cT + col) =
            make_float2(acc[mt][nt][half * 2] * scale,
                        acc[mt][nt][half * 2 + 1] * scale);
      }
    }
}

// ---------------------------------------------------------------------------
// Row softmax -> P bf16 hi/lo (unchanged)
// ---------------------------------------------------------------------------
__global__ void softmax_split_kernel(float* __restrict__ Sc,
                                     bf16* __restrict__ Ph,
                                     bf16* __restrict__ Pl) {
  float* x = Sc + (size_t)blockIdx.x * cT;
  bf16* ph = Ph + (size_t)blockIdx.x * cT;
  bf16* pl = Pl + (size_t)blockIdx.x * cT;
  int tid = threadIdx.x;
  __shared__ float sh[32];
  __shared__ float bc;
  float m = -1e30f;
  for (int c = tid; c < cT; c += 256) m = fmaxf(m, x[c]);
  for (int o = 16; o; o >>= 1) m = fmaxf(m, __shfl_xor_sync(~0u, m, o));
  int w = tid >> 5, lane = tid & 31;
  if (lane == 0) sh[w] = m;
  __syncthreads();
  if (w == 0) {
    m = (lane < 8) ? sh[lane] : -1e30f;
    for (int o = 16; o; o >>= 1) m = fmaxf(m, __shfl_xor_sync(~0u, m, o));
    if (lane == 0) bc = m;
  }
  __syncthreads();
  m = bc;
  float s = 0.f;
  for (int c = tid; c < cT; c += 256) {
    float e = __expf(x[c] - m);
    x[c] = e;
    s += e;
  }
  for (int o = 16; o; o >>= 1) s += __shfl_xor_sync(~0u, s, o);
  __syncthreads();
  if (lane == 0) sh[w] = s;
  __syncthreads();
  if (w == 0) {
    s = (lane < 8) ? sh[lane] : 0.f;
    for (int o = 16; o; o >>= 1) s += __shfl_xor_sync(~0u, s, o);
    if (lane == 0) bc = 1.f / s;
  }
  __syncthreads();
  float inv = bc;
  for (int c = tid; c < cT; c += 256) {
    float p = x[c] * inv;
    bf16 hh = __float2bfloat16(p);
    ph[c] = hh;
    pl[c] = __float2bfloat16(p - __bfloat162float(hh));
  }
}

// ---------------------------------------------------------------------------
// AV on MMA (unchanged)
// ---------------------------------------------------------------------------
#define AV_PSTR 72
#define AV_VSTR 104
#define AV_PARR (64 * AV_PSTR * 2)
#define AV_VARR (64 * AV_VSTR * 2)
#define AV_STAGE (2 * AV_PARR + 2 * AV_VARR)
#define AV_SMEM (2 * AV_STAGE)
__global__ __launch_bounds__(256) void attn_av_mma(
    const bf16* __restrict__ Ph, const bf16* __restrict__ Pl,
    const bf16* __restrict__ Vh, const bf16* __restrict__ Vl,
    bf16* __restrict__ Ohi, bf16* __restrict__ Olo) {
  extern __shared__ char sm[];
  const uint32_t sb = smem_u32(sm);
  const int tid = threadIdx.x, lane = tid & 31, wid = tid >> 5;
  const int bh = blockIdx.x, b = bh >> 4, h = bh & 15;
  const int wm = wid >> 1, wn = wid & 1;

  auto load_chunk = [&](int ct, int buf) {
    int t0 = ct * 64;
    uint32_t base = sb + buf * AV_STAGE;
#pragma unroll
    for (int it = 0; it < 2; it++) {
      int e = tid + it * 256;
      int r = e >> 3, u = e & 7;
      uint32_t so = r * (AV_PSTR * 2) + u * 16;
      size_t po = (size_t)(bh * cL + r) * cT + t0 + u * 8;
      cp_async16(base + so, Ph + po);
      cp_async16(base + AV_PARR + so, Pl + po);
    }
#pragma unroll
    for (int it = 0; it < 3; it++) {
      int e = tid + it * 256;
      int r = e / 12, u = e % 12;
      uint32_t so = r * (AV_VSTR * 2) + u * 16;
      size_t vo = (size_t)(b * cT + t0 + r) * cHHD + h * cHD + u * 8;
      cp_async16(base + 2 * AV_PARR + so, Vh + vo);
      cp_async16(base + 2 * AV_PARR + AV_VARR + so, Vl + vo);
    }
    CP_COMMIT();
  };

  float acc[6][4];
#pragma unroll
  for (int nt = 0; nt < 6; nt++)
#pragma unroll
    for (int j = 0; j < 4; j++) acc[nt][j] = 0.f;

  load_chunk(0, 0);
  for (int ct = 0; ct < 37; ct++) {
    int buf = ct & 1;
    if (ct + 1 < 37) {
      load_chunk(ct + 1, buf ^ 1);
      CP_WAIT(1);
    } else {
      CP_WAIT(0);
    }
    __syncthreads();
    uint32_t base = sb + buf * AV_STAGE;
#pragma unroll
    for (int ks = 0; ks < 4; ks++) {
      uint32_t kb = ks * 16;
      uint32_t ap[4], al[4];
      uint32_t aa = base + (wm * 16 + (lane & 15)) * (AV_PSTR * 2) + kb * 2 +
                    (lane >> 4) * 16;
      ldsm_x4(ap, aa);
      ldsm_x4(al, aa + AV_PARR);
#pragma unroll
      for (int nt = 0; nt < 6; nt++) {
        uint32_t ba = base + 2 * AV_PARR +
                      (kb + ((lane >> 3) & 1) * 8 + (lane & 7)) * (AV_VSTR * 2) +
                      (wn * 48 + nt * 8) * 2;
        uint32_t bv[2], blv[2];
        ldsm_x2_trans(bv, ba);
        ldsm_x2_trans(blv, ba + AV_VARR);
        mma16816(acc[nt], ap, bv);
        mma16816(acc[nt], ap, blv);
        mma16816(acc[nt], al, bv);
      }
    }
    __syncthreads();
  }

#pragma unroll
  for (int half = 0; half < 2; half++) {
    int row = b * cL + wm * 16 + (lane >> 2) + half * 8;
#pragma unroll
    for (int nt = 0; nt < 6; nt++) {
      int col = h * cHD + wn * 48 + nt * 8 + (lane & 3) * 2;
      float v0 = acc[nt][half * 2], v1 = acc[nt][half * 2 + 1];
      bf16 h0 = __float2bfloat16(v0), h1 = __float2bfloat16(v1);
      *(__nv_bfloat162*)(Ohi + (size_t)row * cHHD + col) = __nv_bfloat162(h0, h1);
      *(__nv_bfloat162*)(Olo + (size_t)row * cHHD + col) = __nv_bfloat162(
          __float2bfloat16(v0 - __bfloat162float(h0)),
          __float2bfloat16(v1 - __bfloat162float(h1)));
    }
  }
}

// ---------------------------------------------------------------------------
// LN (no affine) + bf16 hi/lo split
// ---------------------------------------------------------------------------
__global__ void ln_split_kernel(const float* __restrict__ x,
                                bf16* __restrict__ hi, bf16* __restrict__ lo) {
  int row = blockIdx.x;
  const float* xr = x + (size_t)row * cD;
  float s = 0.f, s2 = 0.f;
  for (int c = threadIdx.x; c < cD; c += 256) {
    float v = xr[c];
    s += v; s2 += v * v;
  }
  __shared__ float sh[64];
  for (int o = 16; o; o >>= 1) {
    s += __shfl_xor_sync(~0u, s, o);
    s2 += __shfl_xor_sync(~0u, s2, o);
  }
  int w = threadIdx.x >> 5, lane = threadIdx.x & 31;
  if (lane == 0) { sh[w] = s; sh[w + 32] = s2; }
  __syncthreads();
  if (w == 0) {
    s = (lane < 8) ? sh[lane] : 0.f;
    s2 = (lane < 8) ? sh[lane + 32] : 0.f;
    for (int o = 16; o; o >>= 1) {
      s += __shfl_xor_sync(~0u, s, o);
      s2 += __shfl_xor_sync(~0u, s2, o);
    }
    if (lane == 0) { sh[0] = s; sh[1] = s2; }
  }
  __syncthreads();
  float mean = sh[0] * (1.f / cD);
  float rstd = rsqrtf(sh[1] * (1.f / cD) - mean * mean + cEPS);
  for (int c = threadIdx.x; c < cD; c += 256) {
    float v = (xr[c] - mean) * rstd;
    bf16 h = __float2bfloat16(v);
    hi[(size_t)row * cD + c] = h;
    lo[(size_t)row * cD + c] = __float2bfloat16(v - __bfloat162float(h));
  }
}

// ---------------------------------------------------------------------------
// Weight prep
// ---------------------------------------------------------------------------
__global__ void wprep_kernel(const float* __restrict__ W,
                             const float* __restrict__ g,
                             const float* __restrict__ b,
                             bf16* __restrict__ Whi, bf16* __restrict__ Wlo,
                             float* __restrict__ bias, int Kdim, int Nw) {
  int n = blockIdx.x;
  float bs = 0.f;
  for (int k = threadIdx.x; k < Kdim; k += 256) {
    float w = W[(size_t)k * Nw + n];
    float v = (g != nullptr) ? g[k] * w : w;
    bf16 h = __float2bfloat16(v);
    Whi[(size_t)n * Kdim + k] = h;
    Wlo[(size_t)n * Kdim + k] = __float2bfloat16(v - __bfloat162float(h));
    if (b != nullptr) bs += b[k] * w;
  }
  if (bias != nullptr) {
    __shared__ float sh[8];
    for (int o = 16; o; o >>= 1) bs += __shfl_xor_sync(~0u, bs, o);
    int w8 = threadIdx.x >> 5, lane = threadIdx.x & 31;
    if (lane == 0) sh[w8] = bs;
    __syncthreads();
    if (threadIdx.x == 0) {
      float t = 0.f;
      for (int i = 0; i < 8; i++) t += sh[i];
      bias[n] = t;
    }
  }
}

// ---------------------------------------------------------------------------
// Broadcast latents
// ---------------------------------------------------------------------------
__global__ void bcast_latents_kernel(const float* __restrict__ lat,
                                     float* __restrict__ out) {
  int idx = blockIdx.x * 256 + threadIdx.x;
  out[idx] = lat[idx % (cL * cD)];
}

// ---------------------------------------------------------------------------
// Final LayerNorm with affine
// ---------------------------------------------------------------------------
__global__ void ln_rows_kernel(const float* __restrict__ x,
                               float* __restrict__ y,
                               const float* __restrict__ g,
                               const float* __restrict__ b) {
  int row = blockIdx.x;
  const float* xr = x + (size_t)row * cD;
  float* yr = y + (size_t)row * cD;
  float s = 0.f, s2 = 0.f;
  for (int c = threadIdx.x; c < cD; c += 256) {
    float v = xr[c];
    s += v; s2 += v * v;
  }
  __shared__ float sh[64];
  for (int o = 16; o; o >>= 1) {
    s += __shfl_xor_sync(~0u, s, o);
    s2 += __shfl_xor_sync(~0u, s2, o);
  }
  int w = threadIdx.x >> 5, lane = threadIdx.x & 31;
  if (lane == 0) { sh[w] = s; sh[w + 32] = s2; }
  __syncthreads();
  if (w == 0) {
    s = (lane < 8) ? sh[lane] : 0.f;
    s2 = (lane < 8) ? sh[lane + 32] : 0.f;
    for (int o = 16; o; o >>= 1) {
      s += __shfl_xor_sync(~0u, s, o);
      s2 += __shfl_xor_sync(~0u, s2, o);
    }
    if (lane == 0) { sh[0] = s; sh[1] = s2; }
  }
  __syncthreads();
  float mean = sh[0] * (1.f / cD);
  float rstd = rsqrtf(sh[1] * (1.f / cD) - mean * mean + cEPS);
  for (int c = threadIdx.x; c < cD; c += 256)
    yr[c] = (xr[c] - mean) * rstd * g[c] + b[c];
}

// ---------------------------------------------------------------------------
// Per-head LN -> bf16 hi/lo
// ---------------------------------------------------------------------------
__global__ void ln_head_split_kernel(const float* __restrict__ x,
                                     const float* __restrict__ g,
                                     const float* __restrict__ b,
                                     bf16* __restrict__ hi,
                                     bf16* __restrict__ lo, int nrows) {
  int r = blockIdx.x * 4 + (threadIdx.x >> 5);
  if (r >= nrows) return;
  int lane = threadIdx.x & 31;
  const float* xr = x + (size_t)r * cHD;
  float v0 = xr[lane], v1 = xr[lane + 32], v2 = xr[lane + 64];
  float s = v0 + v1 + v2;
  float s2 = v0 * v0 + v1 * v1 + v2 * v2;
  for (int o = 16; o; o >>= 1) {
    s += __shfl_xor_sync(~0u, s, o);
    s2 += __shfl_xor_sync(~0u, s2, o);
  }
  float mean = s * (1.f / 96.f);
  float rstd = rsqrtf(s2 * (1.f / 96.f) - mean * mean + cEPS);
  float y0 = (v0 - mean) * rstd * g[lane] + b[lane];
  float y1 = (v1 - mean) * rstd * g[lane + 32] + b[lane + 32];
  float y2 = (v2 - mean) * rstd * g[lane + 64] + b[lane + 64];
  bf16* hr = hi + (size_t)r * cHD;
  bf16* lr = lo + (size_t)r * cHD;
  bf16 h0 = __float2bfloat16(y0), h1 = __float2bfloat16(y1),
       h2 = __float2bfloat16(y2);
  hr[lane] = h0; hr[lane + 32] = h1; hr[lane + 64] = h2;
  lr[lane] = __float2bfloat16(y0 - __bfloat162float(h0));
  lr[lane + 32] = __float2bfloat16(y1 - __bfloat162float(h1));
  lr[lane + 64] = __float2bfloat16(y2 - __bfloat162float(h2));
}

// ---------------------------------------------------------------------------
// Host orchestration
// ---------------------------------------------------------------------------
extern "C" void kernel_launch(void* const* d_in, const int* in_sizes, int n_in,
                              void* d_out, int out_size) {
  (void)in_sizes; (void)n_in; (void)out_size;
  const float* context = (const float*)d_in[0];
  const float* latents = (const float*)d_in[1];
  const float* ctx_g = (const float*)d_in[2];
  const float* ctx_b = (const float*)d_in[3];
  const float* lat_g = (const float*)d_in[4];
  const float* lat_b = (const float*)d_in[5];
  const float* q_g = (const float*)d_in[6];
  const float* q_b = (const float*)d_in[7];
  const float* k_g = (const float*)d_in[8];
  const float* k_b = (const float*)d_in[9];
  const float* Wq = (const float*)d_in[10];
  const float* Wk = (const float*)d_in[11];
  const float* Wv = (const float*)d_in[12];
  const float* Wo = (const float*)d_in[13];
  const float* mlp_g = (const float*)d_in[14];
  const float* mlp_b = (const float*)d_in[15];
  const float* Wfc = (const float*)d_in[16];
  const float* Wcp = (const float*)d_in[17];
  const float* f_g = (const float*)d_in[18];
  const float* f_b = (const float*)d_in[19];
  float* out = (float*)d_out;

#define SYM(var, sym) cudaGetSymbolAddress((void**)&var, sym)
  bf16 *ctxhi, *ctxlo, *lnhi, *lnlo, *atthi, *attlo, *mlphi, *mlplo;
  bf16 *qhi, *qlo, *khi, *klo, *vhi, *vlo, *phi, *plo;
  bf16 *wqh, *wql, *wkch, *wkcl, *wklh, *wkll, *wvch, *wvcl, *wvlh, *wvll,
      *woh, *wol, *wfch, *wfcl, *wcph, *wcpl;
  float *bQ, *bKc, *bKl, *bVc, *bVl, *bFc;
  float *lat, *Qp, *Kp, *Scp;
  SYM(ctxhi, g_ctx_hi); SYM(ctxlo, g_ctx_lo);
  SYM(lnhi, g_latln_hi); SYM(lnlo, g_latln_lo);
  SYM(atthi, g_att_hi); SYM(attlo, g_att_lo);
  SYM(mlphi, g_mlp_hi); SYM(mlplo, g_mlp_lo);
  SYM(qhi, g_Q_hi); SYM(qlo, g_Q_lo);
  SYM(khi, g_K_hi); SYM(klo, g_K_lo);
  SYM(vhi, g_V_hi); SYM(vlo, g_V_lo);
  SYM(phi, g_P_hi); SYM(plo, g_P_lo);
  SYM(wqh, g_wq_hi); SYM(wql, g_wq_lo);
  SYM(wkch, g_wkc_hi); SYM(wkcl, g_wkc_lo);
  SYM(wklh, g_wkl_hi); SYM(wkll, g_wkl_lo);
  SYM(wvch, g_wvc_hi); SYM(wvcl, g_wvc_lo);
  SYM(wvlh, g_wvl_hi); SYM(wvll, g_wvl_lo);
  SYM(woh, g_wo_hi); SYM(wol, g_wo_lo);
  SYM(wfch, g_wfc_hi); SYM(wfcl, g_wfc_lo);
  SYM(wcph, g_wcp_hi); SYM(wcpl, g_wcp_lo);
  SYM(bQ, g_biasQ); SYM(bKc, g_biasKc); SYM(bKl, g_biasKl);
  SYM(bVc, g_biasVc); SYM(bVl, g_biasVl); SYM(bFc, g_biasFc);
  SYM(lat, g_lat); SYM(Qp, g_Q); SYM(Kp, g_K); SYM(Scp, g_scores);
#undef SYM

  cudaFuncSetAttribute(mma_gemm_split,
                       cudaFuncAttributeMaxDynamicSharedMemorySize, MG_SMEM);
  cudaFuncSetAttribute(fused_kv_gemm,
                       cudaFuncAttributeMaxDynamicSharedMemorySize, FK_SMEM);
  cudaFuncSetAttribute(attn_scores_mma,
                       cudaFuncAttributeMaxDynamicSharedMemorySize, SCM_SMEM);
  cudaFuncSetAttribute(attn_av_mma,
                       cudaFuncAttributeMaxDynamicSharedMemorySize, AV_SMEM);

  // launches 0,1
  ln_split_kernel<<<cMCTX, 256>>>(context, ctxhi, ctxlo);
  bcast_latents_kernel<<<(cML * cD) / 256, 256>>>(latents, lat);

  auto mma = [&](const bf16* Ah, const bf16* Al, const bf16* Bh,
                 const bf16* Bl, const float* bias, const float* R, float* C,
                 bf16* Ch, bf16* Cl, int M, int N, int Kd, int relu, int rpbIn,
                 int rpbOut, int rowOff) {
    dim3 grid(N / 128, M / 128);
    mma_gemm_split<<<grid, 256, MG_SMEM>>>(Ah, Al, Bh, Bl, bias, R, C, Ch, Cl,
                                           Kd, N, relu, rpbIn, rpbOut, rowOff);
  };

  for (int i = 0; i < cDEPTH; i++) {
    const float* Wq_i = Wq + (size_t)i * cD * cHHD;
    const float* Wk_i = Wk + (size_t)i * cD * cHHD;
    const float* Wv_i = Wv + (size_t)i * cD * cHHD;
    const float* Wo_i = Wo + (size_t)i * cHHD * cD;
    const float* Wfc_i = Wfc + (size_t)i * cD * cI;
    const float* Wcp_i = Wcp + (size_t)i * cI * cD;
    const float* lg = lat_g + i * cD;
    const float* lb = lat_b + i * cD;

    // launches 2,3: ctx weight preps (so launch 5 below is the big GEMM)
    wprep_kernel<<<cHHD, 256>>>(Wk_i, ctx_g + i * cD, ctx_b + i * cD, wkch,
                                wkcl, bKc, cD, cHHD);
    wprep_kernel<<<cHHD, 256>>>(Wv_i, ctx_g + i * cD, ctx_b + i * cD, wvch,
                                wvcl, bVc, cD, cHHD);
    // launch 4: LN(latents)
    ln_split_kernel<<<cML, 256>>>(lat, lnhi, lnlo);

    // launch 5 (layer 0): fused ctx K+V projection  << ncu target >>
    fused_kv_gemm<<<dim3(cHHD / 128, cMCTX / 128), 512, FK_SMEM>>>(
        ctxhi, ctxlo, wkch, wkcl, wvch, wvcl, bKc, bVc, Kp, vhi, vlo, cS, cT,
        0);

    // remaining weight preps
    wprep_kernel<<<cHHD, 256>>>(Wq_i, lg, lb, wqh, wql, bQ, cD, cHHD);
    wprep_kernel<<<cHHD, 256>>>(Wk_i, lg, lb, wklh, wkll, bKl, cD, cHHD);
    wprep_kernel<<<cHHD, 256>>>(Wv_i, lg, lb, wvlh, wvll, bVl, cD, cHHD);

    // Q (fp32 out for per-head LN)
    mma(lnhi, lnlo, wqh, wql, bQ, nullptr, Qp, nullptr, nullptr, cML, cHHD, cD,
        0, cML, cML, 0);
    // latent K+V rows, appended at offset cS
    fused_kv_gemm<<<dim3(cHHD / 128, cML / 128), 512, FK_SMEM>>>(
        lnhi, lnlo, wklh, wkll, wvlh, wvll, bKl, bVl, Kp, vhi, vlo, cL, cT,
        cS);

    // per-head q/k LN -> hi/lo
    ln_head_split_kernel<<<(cML * cH) / 4, 128>>>(Qp, q_g + i * cHD,
                                                  q_b + i * cHD, qhi, qlo,
                                                  cML * cH);
    ln_head_split_kernel<<<(cB * cT * cH) / 4, 128>>>(Kp, k_g + i * cHD,
                                                      k_b + i * cHD, khi, klo,
                                                      cB * cT * cH);

    // attention on MMA
    attn_scores_mma<<<dim3(cT / 64, cB * cH), 256, SCM_SMEM>>>(qhi, qlo, khi,
                                                               klo, Scp);
    softmax_split_kernel<<<cB * cH * cL, 256>>>(Scp, phi, plo);
    attn_av_mma<<<cB * cH, 256, AV_SMEM>>>(phi, plo, vhi, vlo, atthi, attlo);

    // lat = att @ Wo + lat
    wprep_kernel<<<cD, 256>>>(Wo_i, nullptr, nullptr, woh, wol, nullptr, cHHD,
                              cD);
    mma(atthi, attlo, woh, wol, nullptr, lat, lat, nullptr, nullptr, cML, cD,
        cHHD, 0, cML, cML, 0);

    // MLP
    ln_split_kernel<<<cML, 256>>>(lat, lnhi, lnlo);
    wprep_kernel<<<cI, 256>>>(Wfc_i, mlp_g + i * cD, mlp_b + i * cD, wfch, wfcl,
                              bFc, cD, cI);
    mma(lnhi, lnlo, wfch, wfcl, bFc, nullptr, nullptr, mlphi, mlplo, cML, cI,
        cD, 1, cML, cML, 0);
    wprep_kernel<<<cD, 256>>>(Wcp_i, nullptr, nullptr, wcph, wcpl, nullptr, cI,
                              cD);
    mma(mlphi, mlplo, wcph, wcpl, nullptr, lat, lat, nullptr, nullptr, cML, cD,
        cI, 0, cML, cML, 0);
  }

  ln_rows_kernel<<<cML, 256>>>(lat, out, f_g, f_b);
}